// round 11
// baseline (speedup 1.0000x reference)
#include <cuda_runtime.h>
#include <math.h>

#define BN   1024
#define TSTEPS 48
#define NA   35
#define NM   18
#define NN   53
#define HH   32
#define CTXD 60
#define DD   92      // HH + CTXD
#define BPB  4
#define NTHREADS 1024
#define NWARPS (NTHREADS / 32)
#define ATTP 56      // padded att row (multiple of 4, keeps float4 alignment)
#define KP   33      // padded k-dim for outvP scatter (8-way instead of 16-way)
#define GATHN (BPB * NN * 16)   // 3392 gather elements per buffer
#define MASKED_BASE -1e13f

// ---------------- precomputed (batch/time invariant) ----------------
__device__ float g_base[NN * NN];
__device__ float g_ctx4[NN * 4];

__global__ void setup_kernel(const float* __restrict__ adj,
                             const float* __restrict__ adjn,
                             const float* __restrict__ ctx,
                             const float* __restrict__ a0,
                             const float* __restrict__ a1,
                             const float* __restrict__ a2,
                             const float* __restrict__ a3) {
    const float* A[4] = {a0, a1, a2, a3};
    for (int idx = threadIdx.x; idx < NN * NN; idx += blockDim.x) {
        int i = idx / NN, j = idx % NN;
        int bt = (i < NA ? 0 : 2) + (j < NA ? 0 : 1);
        // mask folded in: masked entries get -1e13 -> leaky -> -2e12 -> expf -> 0
        g_base[idx] = (adj[idx] > 0.0f) ? adjn[idx] * A[bt][2 * DD] : MASKED_BASE;
    }
    for (int idx = threadIdx.x; idx < NN * 4; idx += blockDim.x) {
        int n = idx >> 2, sI = idx & 3;
        int bt;
        if (sI == 0)      bt = n < NA ? 0 : 2;   // src, cols=aqi block
        else if (sI == 1) bt = n < NA ? 1 : 3;   // src, cols=meo block
        else if (sI == 2) bt = n < NA ? 0 : 1;   // dst, rows=aqi block
        else              bt = n < NA ? 2 : 3;   // dst, rows=meo block
        const float* av = A[bt] + (sI < 2 ? HH : DD + HH);
        float acc = 0.f;
        for (int c = 0; c < CTXD; c++) acc += ctx[n * CTXD + c] * av[c];
        g_ctx4[idx] = acc;
    }
}

// ---------------- main persistent kernel ----------------
struct Args {
    const float *X_aqi, *X_meo;
    const float *e_ai, *e_amo, *e_awd, *e_ah;
    const float *e_mw, *e_mid, *e_mmo, *e_mwd, *e_mh;
    const float *W_xa, *W_xm, *W_ua, *W_um;
    const float *a0, *a1, *a2, *a3;
    const float *wihA, *whhA, *bihA, *bhhA;
    const float *wihM, *whhM, *bihM, *bhhM;
    const int *EXa, *EXm;
    float *out;
};

struct SmemLayout {
    // --- float4-accessed arrays first (sizes all divisible by 16B) ---
    float hP[NN][HH][BPB];        // h transposed: (node, k, batch)
    float outvP[NN][KP][BPB];     // GRU input transposed, padded k
    float attri[BPB][NN][HH];     // values
    float att[BPB][NN][ATTP];     // RAW exp rows (unnormalized)
    float in16[2][BPB][NN][16];   // gathered inputs, DOUBLE BUFFERED
    float rs[BPB][NN][2];
    float cs2[2][BPB][NN];        // [ics][bb][j] -> conflict-free lane reads
    float invs[BPB][NN];          // 1/rowsum for deferred normalization
    float Wxa[6 * HH], Wxm[4 * HH];
    float Wua16[16 * HH], Wum16[16 * HH];   // padded to 16 rows (rows 14,15 zero)
    float aS[4][HH], aD[4][HH];
    float ctx4[NN][4];
    // --- scalar-accessed arrays ---  (base now read from global/L1)
    float WihA[HH][96], WhhA[HH][96], WihM[HH][96], WhhM[HH][96];
    float bihA[96], bhhA[96], bihM[96], bhhM[96];
};

__device__ __forceinline__ float sigf(float x) {
    return 1.0f / (1.0f + __expf(-x));
}

__device__ __forceinline__ void fma4(float4& a, const float4& x, float w) {
    a.x += x.x * w; a.y += x.y * w; a.z += x.z * w; a.w += x.w * w;
}

// gather one element of the [BPB][NN][16] input block for timestep tt
__device__ __forceinline__ float gather_val(const Args& A, int bbase, int tt, int idx) {
    int k = idx & 15;
    int n = (idx >> 4) % NN;
    int bb = idx / (16 * NN);
    int b = bbase + bb;
    float v = 0.f;
    if (n < NA) {
        if (k < 6) {
            v = A.X_aqi[((size_t)(b * TSTEPS + tt) * NA + n) * 6 + k];
        } else if (k < 14) {
            int p = (k - 6) >> 1, c = (k - 6) & 1;
            int e = A.EXa[((size_t)(b * TSTEPS + tt) * NA + n) * 4 + p];
            const float* tab = (p == 0) ? A.e_ai : (p == 1) ? A.e_amo : (p == 2) ? A.e_awd : A.e_ah;
            v = tab[e * 2 + c];
        }
    } else {
        int m = n - NA;
        if (k < 4) {
            v = A.X_meo[((size_t)(b * TSTEPS + tt) * NM + m) * 4 + k];
        } else if (k < 14) {
            int p = (k - 4) >> 1, c = (k - 4) & 1;
            int e = A.EXm[((size_t)(b * TSTEPS + tt) * NM + m) * 5 + p];
            const float* tab = (p == 0) ? A.e_mw : (p == 1) ? A.e_mid : (p == 2) ? A.e_mmo
                             : (p == 3) ? A.e_mwd : A.e_mh;
            v = tab[e * 2 + c];
        }
    }
    return v;
}

extern __shared__ __align__(16) char smem_raw[];

__global__ __launch_bounds__(NTHREADS, 1)
void chgat_gru_kernel(Args A) {
    SmemLayout& s = *reinterpret_cast<SmemLayout*>(smem_raw);
    const int tid = threadIdx.x;
    const int lane = tid & 31;
    const int wid = tid >> 5;
    const int bbase = blockIdx.x * BPB;

    // ---- preload weights / constants into smem ----
    for (int i = tid; i < 6 * HH; i += NTHREADS) s.Wxa[i] = A.W_xa[i];
    for (int i = tid; i < 4 * HH; i += NTHREADS) s.Wxm[i] = A.W_xm[i];
    for (int i = tid; i < 14 * HH; i += NTHREADS) { s.Wua16[i] = A.W_ua[i]; s.Wum16[i] = A.W_um[i]; }
    for (int i = tid; i < 2 * HH; i += NTHREADS) { s.Wua16[14 * HH + i] = 0.f; s.Wum16[14 * HH + i] = 0.f; }
    for (int i = tid; i < 4 * HH; i += NTHREADS) {
        int bt = i / HH, o = i % HH;
        const float* av = (bt == 0) ? A.a0 : (bt == 1) ? A.a1 : (bt == 2) ? A.a2 : A.a3;
        s.aS[bt][o] = av[o];
        s.aD[bt][o] = av[DD + o];
    }
    for (int i = tid; i < NN * 4; i += NTHREADS) (&s.ctx4[0][0])[i] = g_ctx4[i];
    for (int i = tid; i < HH * 96; i += NTHREADS) {
        int k = i / 96, g = i % 96;
        s.WihA[k][g] = A.wihA[g * HH + k];
        s.WhhA[k][g] = A.whhA[g * HH + k];
        s.WihM[k][g] = A.wihM[g * HH + k];
        s.WhhM[k][g] = A.whhM[g * HH + k];
    }
    for (int i = tid; i < 96; i += NTHREADS) {
        s.bihA[i] = A.bihA[i]; s.bhhA[i] = A.bhhA[i];
        s.bihM[i] = A.bihM[i]; s.bhhM[i] = A.bhhM[i];
    }
    for (int i = tid; i < NN * HH * BPB; i += NTHREADS) (&s.hP[0][0][0])[i] = 0.f;

    // ---- prime gather for t = 0 into buffer 0 ----
    for (int idx = tid; idx < GATHN; idx += NTHREADS)
        (&s.in16[0][0][0][0])[idx] = gather_val(A, bbase, 0, idx);
    __syncthreads();

    for (int t = 0; t < TSTEPS; t++) {
        const int p = t & 1;
        // ---- stage 2: attri + 4 score dots (float4 broadcast reads of in16) ----
        for (int r = wid; r < BPB * NN; r += NWARPS) {
            int bb = r / NN, n = r % NN;
            const float4* in4 = reinterpret_cast<const float4*>(&s.in16[p][bb][n][0]);
            float4 q0 = in4[0], q1 = in4[1], q2 = in4[2], q3 = in4[3];
            const int o = lane;
            float acc_a, acc_f;
            const float* Wf;
            if (n < NA) {
                acc_a = q0.x * s.Wxa[0 * HH + o] + q0.y * s.Wxa[1 * HH + o]
                      + q0.z * s.Wxa[2 * HH + o] + q0.w * s.Wxa[3 * HH + o]
                      + q1.x * s.Wxa[4 * HH + o] + q1.y * s.Wxa[5 * HH + o];
                Wf = s.Wua16;
            } else {
                acc_a = q0.x * s.Wxm[0 * HH + o] + q0.y * s.Wxm[1 * HH + o]
                      + q0.z * s.Wxm[2 * HH + o] + q0.w * s.Wxm[3 * HH + o];
                Wf = s.Wum16;
            }
            acc_f = q0.x * Wf[0 * HH + o]  + q0.y * Wf[1 * HH + o]
                  + q0.z * Wf[2 * HH + o]  + q0.w * Wf[3 * HH + o]
                  + q1.x * Wf[4 * HH + o]  + q1.y * Wf[5 * HH + o]
                  + q1.z * Wf[6 * HH + o]  + q1.w * Wf[7 * HH + o]
                  + q2.x * Wf[8 * HH + o]  + q2.y * Wf[9 * HH + o]
                  + q2.z * Wf[10 * HH + o] + q2.w * Wf[11 * HH + o]
                  + q3.x * Wf[12 * HH + o] + q3.y * Wf[13 * HH + o];
            s.attri[bb][n][o] = acc_a;
            // four score dot-products (src-aqi, src-meo, dst-aqi, dst-meo views)
            int btS0 = n < NA ? 0 : 2;
            int btS1 = n < NA ? 1 : 3;
            int btD0 = n < NA ? 0 : 1;
            int btD1 = n < NA ? 2 : 3;
            float p0 = acc_f * s.aS[btS0][o];
            float p1 = acc_f * s.aS[btS1][o];
            float p2 = acc_f * s.aD[btD0][o];
            float p3 = acc_f * s.aD[btD1][o];
            #pragma unroll
            for (int d = 16; d > 0; d >>= 1) {
                p0 += __shfl_xor_sync(0xffffffffu, p0, d);
                p1 += __shfl_xor_sync(0xffffffffu, p1, d);
                p2 += __shfl_xor_sync(0xffffffffu, p2, d);
                p3 += __shfl_xor_sync(0xffffffffu, p3, d);
            }
            if (lane == 0) {
                s.rs[bb][n][0] = p0 + s.ctx4[n][0];
                s.rs[bb][n][1] = p1 + s.ctx4[n][1];
                s.cs2[0][bb][n] = p2 + s.ctx4[n][2];
                s.cs2[1][bb][n] = p3 + s.ctx4[n][3];
            }
        }
        __syncthreads();

        // ---- stage 4+5: e row (leaky, no max — logits bounded; mask folded
        //      into base -> exp=0 exactly on masked) + rowsum reciprocal ----
        for (int r = wid; r < BPB * NN; r += NWARPS) {
            int bb = r / NN, i = r % NN;
            float ri0 = s.rs[bb][i][0], ri1 = s.rs[bb][i][1];
            int ics = (i >= NA) ? 1 : 0;
            const float* csrow = s.cs2[ics][bb];
            int j = lane;
            float v0 = (j >= NA ? ri1 : ri0) + csrow[j] + g_base[i * NN + j];
            v0 = (v0 >= 0.f) ? v0 : 0.2f * v0;
            float e0 = __expf(v0);
            int j2 = lane + 32;
            float e1 = 0.f;
            if (j2 < NN) {
                // NOTE: NA=35 > 32, so j2 in {32,33,34} is still an aqi column -> ri0!
                float v = (j2 >= NA ? ri1 : ri0) + csrow[j2] + g_base[i * NN + j2];
                v = (v >= 0.f) ? v : 0.2f * v;
                e1 = __expf(v);
            }
            s.att[bb][i][lane] = e0;
            if (j2 < NN) s.att[bb][i][j2] = e1;
            float ss = e0 + e1;
            #pragma unroll
            for (int d = 16; d > 0; d >>= 1) ss += __shfl_xor_sync(0xffffffffu, ss, d);
            if (lane == 0) s.invs[bb][i] = 1.0f / ss;
        }
        __syncthreads();

        // ---- prefetch gather for t+1 into registers (LDG latency hidden by stage 6) ----
        float pv0 = 0.f, pv1 = 0.f, pv2 = 0.f, pv3 = 0.f;
        const bool havePf = (t + 1 < TSTEPS);
        if (havePf) {
            int i0 = tid;
            pv0 = gather_val(A, bbase, t + 1, i0);
            int i1 = tid + NTHREADS;
            pv1 = gather_val(A, bbase, t + 1, i1);
            int i2 = tid + 2 * NTHREADS;
            pv2 = gather_val(A, bbase, t + 1, i2);
            int i3 = tid + 3 * NTHREADS;
            if (i3 < GATHN) pv3 = gather_val(A, bbase, t + 1, i3);
        }

        // ---- stage 6: outvP = (attE @ attri) * invs ----
        for (int tt = tid; tt < BPB * 27 * 8; tt += NTHREADS) {
            int og = tt % 8;
            int ig = (tt / 8) % 27;
            int bb = tt / (27 * 8);
            int i0 = ig * 2;
            int i1 = i0 + 1;
            bool has1 = (i1 < NN);
            float4 acc0 = make_float4(0.f, 0.f, 0.f, 0.f);
            float4 acc1 = make_float4(0.f, 0.f, 0.f, 0.f);
            const float* r0 = &s.att[bb][i0][0];
            const float* r1 = &s.att[bb][has1 ? i1 : i0][0];
            const float* atrb = &s.attri[bb][0][0];
            #pragma unroll 4
            for (int j4 = 0; j4 + 4 <= NN; j4 += 4) {
                float4 a0q = *reinterpret_cast<const float4*>(&r0[j4]);
                float4 a1q = *reinterpret_cast<const float4*>(&r1[j4]);
                float4 v0 = *reinterpret_cast<const float4*>(&atrb[(j4 + 0) * HH + og * 4]);
                float4 v1 = *reinterpret_cast<const float4*>(&atrb[(j4 + 1) * HH + og * 4]);
                float4 v2 = *reinterpret_cast<const float4*>(&atrb[(j4 + 2) * HH + og * 4]);
                float4 v3 = *reinterpret_cast<const float4*>(&atrb[(j4 + 3) * HH + og * 4]);
                fma4(acc0, v0, a0q.x); fma4(acc0, v1, a0q.y);
                fma4(acc0, v2, a0q.z); fma4(acc0, v3, a0q.w);
                fma4(acc1, v0, a1q.x); fma4(acc1, v1, a1q.y);
                fma4(acc1, v2, a1q.z); fma4(acc1, v3, a1q.w);
            }
            {   // tail j = 52
                const int j = NN - 1;
                float4 v0 = *reinterpret_cast<const float4*>(&atrb[j * HH + og * 4]);
                fma4(acc0, v0, r0[j]);
                fma4(acc1, v0, r1[j]);
            }
            float inv0 = s.invs[bb][i0];
            int k0 = og * 4;
            s.outvP[i0][k0 + 0][bb] = acc0.x * inv0;
            s.outvP[i0][k0 + 1][bb] = acc0.y * inv0;
            s.outvP[i0][k0 + 2][bb] = acc0.z * inv0;
            s.outvP[i0][k0 + 3][bb] = acc0.w * inv0;
            if (has1) {
                float inv1 = s.invs[bb][i1];
                s.outvP[i1][k0 + 0][bb] = acc1.x * inv1;
                s.outvP[i1][k0 + 1][bb] = acc1.y * inv1;
                s.outvP[i1][k0 + 2][bb] = acc1.z * inv1;
                s.outvP[i1][k0 + 3][bb] = acc1.w * inv1;
            }
        }

        // ---- publish prefetched inputs for t+1 (before the stage-6 barrier) ----
        if (havePf) {
            float* dst = &s.in16[p ^ 1][0][0][0];
            dst[tid] = pv0;
            dst[tid + NTHREADS] = pv1;
            dst[tid + 2 * NTHREADS] = pv2;
            if (tid + 3 * NTHREADS < GATHN) dst[tid + 3 * NTHREADS] = pv3;
        }
        __syncthreads();

        // ---- stage 7: GRU (warp per node, float4 over batches) ----
        // NOTE: deterministic node<->warp mapping means hP[n][*][*] is written and
        // re-read by the SAME warp next timestep -> no barrier needed after this stage.
        for (int n = wid; n < NN; n += NWARPS) {
            bool isA = n < NA;
            const float (*Wih)[96] = isA ? s.WihA : s.WihM;
            const float (*Whh)[96] = isA ? s.WhhA : s.WhhM;
            const float* bih = isA ? s.bihA : s.bihM;
            const float* bhh = isA ? s.bhhA : s.bhhM;
            float bir = bih[lane], biz = bih[32 + lane], bin = bih[64 + lane];
            float bhr = bhh[lane], bhz = bhh[32 + lane], bhn = bhh[64 + lane];
            float4 gir = make_float4(bir, bir, bir, bir);
            float4 giz = make_float4(biz, biz, biz, biz);
            float4 gin = make_float4(bin, bin, bin, bin);
            float4 ghr = make_float4(bhr, bhr, bhr, bhr);
            float4 ghz = make_float4(bhz, bhz, bhz, bhz);
            float4 ghn = make_float4(bhn, bhn, bhn, bhn);
            float4 hold = *reinterpret_cast<const float4*>(&s.hP[n][lane][0]);
            #pragma unroll 4
            for (int k = 0; k < HH; k++) {
                float wr = Wih[k][lane], wz = Wih[k][32 + lane], wn = Wih[k][64 + lane];
                float vr = Whh[k][lane], vz = Whh[k][32 + lane], vn = Whh[k][64 + lane];
                float4 x4 = *reinterpret_cast<const float4*>(&s.outvP[n][k][0]);
                float4 h4 = *reinterpret_cast<const float4*>(&s.hP[n][k][0]);
                fma4(gir, x4, wr); fma4(giz, x4, wz); fma4(gin, x4, wn);
                fma4(ghr, h4, vr); fma4(ghz, h4, vz); fma4(ghn, h4, vn);
            }
            float4 hnew;
            {
                float r0 = sigf(gir.x + ghr.x), z0 = sigf(giz.x + ghz.x);
                hnew.x = (1.f - z0) * tanhf(gin.x + r0 * ghn.x) + z0 * hold.x;
                float r1 = sigf(gir.y + ghr.y), z1 = sigf(giz.y + ghz.y);
                hnew.y = (1.f - z1) * tanhf(gin.y + r1 * ghn.y) + z1 * hold.y;
                float r2 = sigf(gir.z + ghr.z), z2 = sigf(giz.z + ghz.z);
                hnew.z = (1.f - z2) * tanhf(gin.z + r2 * ghn.z) + z2 * hold.z;
                float r3 = sigf(gir.w + ghr.w), z3 = sigf(giz.w + ghz.w);
                hnew.w = (1.f - z3) * tanhf(gin.w + r3 * ghn.w) + z3 * hold.w;
            }
            __syncwarp();
            *reinterpret_cast<float4*>(&s.hP[n][lane][0]) = hnew;
        }
        // no __syncthreads here; next-iter stage 2 reads in16[p^1] which was
        // published before the stage-6 barrier, and attri/rs/cs2 writes of t+1
        // are ordered against stage-6 reads of t by that same barrier.
    }
    __syncthreads();

    // ---- write output: h_aqi [B,35,32] then h_meo [B,18,32] ----
    for (int idx = tid; idx < BPB * NN * HH; idx += NTHREADS) {
        int o = idx & 31;
        int n = (idx >> 5) % NN;
        int bb = idx / (NN * HH);
        int b = bbase + bb;
        float v = s.hP[n][o][bb];
        if (n < NA) A.out[((size_t)b * NA + n) * HH + o] = v;
        else        A.out[(size_t)BN * NA * HH + ((size_t)b * NM + (n - NA)) * HH + o] = v;
    }
}

extern "C" void kernel_launch(void* const* d_in, const int* in_sizes, int n_in,
                              void* d_out, int out_size) {
    (void)in_sizes; (void)n_in; (void)out_size;
    const float* X_aqi = (const float*)d_in[0];
    const float* X_meo = (const float*)d_in[1];
    const float* ctx   = (const float*)d_in[2];
    const float* adj   = (const float*)d_in[3];
    const float* adjn  = (const float*)d_in[4];
    const float* e_ai  = (const float*)d_in[5];
    const float* e_amo = (const float*)d_in[6];
    const float* e_awd = (const float*)d_in[7];
    const float* e_ah  = (const float*)d_in[8];
    const float* e_mw  = (const float*)d_in[9];
    const float* e_mid = (const float*)d_in[10];
    const float* e_mmo = (const float*)d_in[11];
    const float* e_mwd = (const float*)d_in[12];
    const float* e_mh  = (const float*)d_in[13];
    const float* W_xa  = (const float*)d_in[14];
    const float* W_xm  = (const float*)d_in[15];
    const float* W_ua  = (const float*)d_in[16];
    const float* W_um  = (const float*)d_in[17];
    const float* a0    = (const float*)d_in[18];
    const float* a1    = (const float*)d_in[19];
    const float* a2    = (const float*)d_in[20];
    const float* a3    = (const float*)d_in[21];
    const float* wihA  = (const float*)d_in[22];
    const float* whhA  = (const float*)d_in[23];
    const float* bihA  = (const float*)d_in[24];
    const float* bhhA  = (const float*)d_in[25];
    const float* wihM  = (const float*)d_in[26];
    const float* whhM  = (const float*)d_in[27];
    const float* bihM  = (const float*)d_in[28];
    const float* bhhM  = (const float*)d_in[29];
    const int*   EXa   = (const int*)d_in[30];
    const int*   EXm   = (const int*)d_in[31];

    setup_kernel<<<1, 256>>>(adj, adjn, ctx, a0, a1, a2, a3);

    Args A;
    A.X_aqi = X_aqi; A.X_meo = X_meo;
    A.e_ai = e_ai; A.e_amo = e_amo; A.e_awd = e_awd; A.e_ah = e_ah;
    A.e_mw = e_mw; A.e_mid = e_mid; A.e_mmo = e_mmo; A.e_mwd = e_mwd; A.e_mh = e_mh;
    A.W_xa = W_xa; A.W_xm = W_xm; A.W_ua = W_ua; A.W_um = W_um;
    A.a0 = a0; A.a1 = a1; A.a2 = a2; A.a3 = a3;
    A.wihA = wihA; A.whhA = whhA; A.bihA = bihA; A.bhhA = bhhA;
    A.wihM = wihM; A.whhM = whhM; A.bihM = bihM; A.bhhM = bhhM;
    A.EXa = EXa; A.EXm = EXm;
    A.out = (float*)d_out;

    int smem = (int)sizeof(SmemLayout);
    cudaFuncSetAttribute(chgat_gru_kernel, cudaFuncAttributeMaxDynamicSharedMemorySize, smem);
    chgat_gru_kernel<<<BN / BPB, NTHREADS, smem>>>(A);
}

// round 12
// speedup vs baseline: 1.0356x; 1.0356x over previous
#include <cuda_runtime.h>
#include <math.h>

#define BN   1024
#define TSTEPS 48
#define NA   35
#define NM   18
#define NN   53
#define HH   32
#define CTXD 60
#define DD   92      // HH + CTXD
#define BPB  4
#define NTHREADS 1024
#define NWARPS (NTHREADS / 32)
#define ATTP 56      // padded att row (multiple of 4, keeps float4 alignment)
#define KP   33      // padded k-dim for outvP scatter (8-way instead of 16-way)
#define MASKED_BASE -1e13f

// ---------------- precomputed (batch/time invariant) ----------------
__device__ float g_base[NN * NN];
__device__ float g_ctx4[NN * 4];

__global__ void setup_kernel(const float* __restrict__ adj,
                             const float* __restrict__ adjn,
                             const float* __restrict__ ctx,
                             const float* __restrict__ a0,
                             const float* __restrict__ a1,
                             const float* __restrict__ a2,
                             const float* __restrict__ a3) {
    const float* A[4] = {a0, a1, a2, a3};
    for (int idx = threadIdx.x; idx < NN * NN; idx += blockDim.x) {
        int i = idx / NN, j = idx % NN;
        int bt = (i < NA ? 0 : 2) + (j < NA ? 0 : 1);
        // mask folded in: masked entries get -1e13 -> leaky -> -2e12 -> expf -> 0
        g_base[idx] = (adj[idx] > 0.0f) ? adjn[idx] * A[bt][2 * DD] : MASKED_BASE;
    }
    for (int idx = threadIdx.x; idx < NN * 4; idx += blockDim.x) {
        int n = idx >> 2, sI = idx & 3;
        int bt;
        if (sI == 0)      bt = n < NA ? 0 : 2;   // src, cols=aqi block
        else if (sI == 1) bt = n < NA ? 1 : 3;   // src, cols=meo block
        else if (sI == 2) bt = n < NA ? 0 : 1;   // dst, rows=aqi block
        else              bt = n < NA ? 2 : 3;   // dst, rows=meo block
        const float* av = A[bt] + (sI < 2 ? HH : DD + HH);
        float acc = 0.f;
        for (int c = 0; c < CTXD; c++) acc += ctx[n * CTXD + c] * av[c];
        g_ctx4[idx] = acc;
    }
}

// ---------------- main persistent kernel ----------------
struct Args {
    const float *X_aqi, *X_meo;
    const float *e_ai, *e_amo, *e_awd, *e_ah;
    const float *e_mw, *e_mid, *e_mmo, *e_mwd, *e_mh;
    const float *W_xa, *W_xm, *W_ua, *W_um;
    const float *a0, *a1, *a2, *a3;
    const float *wihA, *whhA, *bihA, *bhhA;
    const float *wihM, *whhM, *bihM, *bhhM;
    const int *EXa, *EXm;
    float *out;
};

struct SmemLayout {
    // --- float4-accessed arrays first (sizes all divisible by 16B) ---
    float hP[NN][HH][BPB];       // h transposed: (node, k, batch)
    float outvP[NN][KP][BPB];    // GRU input transposed, padded k
    float attri[BPB][NN][HH];    // values
    float att[BPB][NN][ATTP];    // RAW exp rows (unnormalized)
    float in16[BPB][NN][16];     // gathered inputs (padded 16)
    float rs[BPB][NN][2];
    float cs2[2][BPB][NN];       // [ics][bb][j] -> conflict-free lane reads
    float invs[BPB][NN];         // 1/rowsum for deferred normalization
    float Wxa[6 * HH], Wxm[4 * HH];
    float Wua16[16 * HH], Wum16[16 * HH];   // padded to 16 rows (rows 14,15 zero)
    float aS[4][HH], aD[4][HH];
    float ctx4[NN][4];
    // --- scalar-accessed arrays ---
    float base[NN * NN];
    float WihA[HH][96], WhhA[HH][96], WihM[HH][96], WhhM[HH][96];
    float bihA[96], bhhA[96], bihM[96], bhhM[96];
};

__device__ __forceinline__ float sigf(float x) {
    return 1.0f / (1.0f + __expf(-x));
}

__device__ __forceinline__ float tanh_fast(float x) {
    float y;
    asm("tanh.approx.f32 %0, %1;" : "=f"(y) : "f"(x));
    return y;
}

__device__ __forceinline__ void fma4(float4& a, const float4& x, float w) {
    a.x += x.x * w; a.y += x.y * w; a.z += x.z * w; a.w += x.w * w;
}

extern __shared__ __align__(16) char smem_raw[];

__global__ __launch_bounds__(NTHREADS, 1)
void chgat_gru_kernel(Args A) {
    SmemLayout& s = *reinterpret_cast<SmemLayout*>(smem_raw);
    const int tid = threadIdx.x;
    const int lane = tid & 31;
    const int wid = tid >> 5;
    const int bbase = blockIdx.x * BPB;

    // ---- preload weights / constants into smem ----
    for (int i = tid; i < 6 * HH; i += NTHREADS) s.Wxa[i] = A.W_xa[i];
    for (int i = tid; i < 4 * HH; i += NTHREADS) s.Wxm[i] = A.W_xm[i];
    for (int i = tid; i < 14 * HH; i += NTHREADS) { s.Wua16[i] = A.W_ua[i]; s.Wum16[i] = A.W_um[i]; }
    for (int i = tid; i < 2 * HH; i += NTHREADS) { s.Wua16[14 * HH + i] = 0.f; s.Wum16[14 * HH + i] = 0.f; }
    for (int i = tid; i < 4 * HH; i += NTHREADS) {
        int bt = i / HH, o = i % HH;
        const float* av = (bt == 0) ? A.a0 : (bt == 1) ? A.a1 : (bt == 2) ? A.a2 : A.a3;
        s.aS[bt][o] = av[o];
        s.aD[bt][o] = av[DD + o];
    }
    for (int i = tid; i < NN * 4; i += NTHREADS) (&s.ctx4[0][0])[i] = g_ctx4[i];
    for (int i = tid; i < NN * NN; i += NTHREADS) s.base[i] = g_base[i];
    for (int i = tid; i < HH * 96; i += NTHREADS) {
        int k = i / 96, g = i % 96;
        s.WihA[k][g] = A.wihA[g * HH + k];
        s.WhhA[k][g] = A.whhA[g * HH + k];
        s.WihM[k][g] = A.wihM[g * HH + k];
        s.WhhM[k][g] = A.whhM[g * HH + k];
    }
    for (int i = tid; i < 96; i += NTHREADS) {
        s.bihA[i] = A.bihA[i]; s.bhhA[i] = A.bhhA[i];
        s.bihM[i] = A.bihM[i]; s.bhhM[i] = A.bhhM[i];
    }
    for (int i = tid; i < NN * HH * BPB; i += NTHREADS) (&s.hP[0][0][0])[i] = 0.f;
    __syncthreads();

    for (int t = 0; t < TSTEPS; t++) {
        // ---- stage 1: gather in16 = [x | embeddings | 0,0] ----
        for (int idx = tid; idx < BPB * NN * 16; idx += NTHREADS) {
            int k = idx & 15;
            int n = (idx >> 4) % NN;
            int bb = idx / (16 * NN);
            int b = bbase + bb;
            float v = 0.f;
            if (n < NA) {
                if (k < 6) {
                    v = A.X_aqi[((size_t)(b * TSTEPS + t) * NA + n) * 6 + k];
                } else if (k < 14) {
                    int p = (k - 6) >> 1, c = (k - 6) & 1;
                    int e = A.EXa[((size_t)(b * TSTEPS + t) * NA + n) * 4 + p];
                    const float* tab = (p == 0) ? A.e_ai : (p == 1) ? A.e_amo : (p == 2) ? A.e_awd : A.e_ah;
                    v = tab[e * 2 + c];
                }
            } else {
                int m = n - NA;
                if (k < 4) {
                    v = A.X_meo[((size_t)(b * TSTEPS + t) * NM + m) * 4 + k];
                } else if (k < 14) {
                    int p = (k - 4) >> 1, c = (k - 4) & 1;
                    int e = A.EXm[((size_t)(b * TSTEPS + t) * NM + m) * 5 + p];
                    const float* tab = (p == 0) ? A.e_mw : (p == 1) ? A.e_mid : (p == 2) ? A.e_mmo
                                     : (p == 3) ? A.e_mwd : A.e_mh;
                    v = tab[e * 2 + c];
                }
            }
            s.in16[bb][n][k] = v;
        }
        __syncthreads();

        // ---- stage 2: attri + 4 score dots (float4 broadcast reads of in16) ----
        for (int r = wid; r < BPB * NN; r += NWARPS) {
            int bb = r / NN, n = r % NN;
            const float4* in4 = reinterpret_cast<const float4*>(&s.in16[bb][n][0]);
            float4 q0 = in4[0], q1 = in4[1], q2 = in4[2], q3 = in4[3];
            const int o = lane;
            float acc_a, acc_f;
            const float* Wf;
            if (n < NA) {
                acc_a = q0.x * s.Wxa[0 * HH + o] + q0.y * s.Wxa[1 * HH + o]
                      + q0.z * s.Wxa[2 * HH + o] + q0.w * s.Wxa[3 * HH + o]
                      + q1.x * s.Wxa[4 * HH + o] + q1.y * s.Wxa[5 * HH + o];
                Wf = s.Wua16;
            } else {
                acc_a = q0.x * s.Wxm[0 * HH + o] + q0.y * s.Wxm[1 * HH + o]
                      + q0.z * s.Wxm[2 * HH + o] + q0.w * s.Wxm[3 * HH + o];
                Wf = s.Wum16;
            }
            acc_f = q0.x * Wf[0 * HH + o]  + q0.y * Wf[1 * HH + o]
                  + q0.z * Wf[2 * HH + o]  + q0.w * Wf[3 * HH + o]
                  + q1.x * Wf[4 * HH + o]  + q1.y * Wf[5 * HH + o]
                  + q1.z * Wf[6 * HH + o]  + q1.w * Wf[7 * HH + o]
                  + q2.x * Wf[8 * HH + o]  + q2.y * Wf[9 * HH + o]
                  + q2.z * Wf[10 * HH + o] + q2.w * Wf[11 * HH + o]
                  + q3.x * Wf[12 * HH + o] + q3.y * Wf[13 * HH + o];
            s.attri[bb][n][o] = acc_a;
            // four score dot-products (src-aqi, src-meo, dst-aqi, dst-meo views)
            int btS0 = n < NA ? 0 : 2;
            int btS1 = n < NA ? 1 : 3;
            int btD0 = n < NA ? 0 : 1;
            int btD1 = n < NA ? 2 : 3;
            float p0 = acc_f * s.aS[btS0][o];
            float p1 = acc_f * s.aS[btS1][o];
            float p2 = acc_f * s.aD[btD0][o];
            float p3 = acc_f * s.aD[btD1][o];
            #pragma unroll
            for (int d = 16; d > 0; d >>= 1) {
                p0 += __shfl_xor_sync(0xffffffffu, p0, d);
                p1 += __shfl_xor_sync(0xffffffffu, p1, d);
                p2 += __shfl_xor_sync(0xffffffffu, p2, d);
                p3 += __shfl_xor_sync(0xffffffffu, p3, d);
            }
            if (lane == 0) {
                s.rs[bb][n][0] = p0 + s.ctx4[n][0];
                s.rs[bb][n][1] = p1 + s.ctx4[n][1];
                s.cs2[0][bb][n] = p2 + s.ctx4[n][2];
                s.cs2[1][bb][n] = p3 + s.ctx4[n][3];
            }
        }
        __syncthreads();

        // ---- stage 4+5: e row (leaky, no max — logits bounded; mask folded
        //      into base -> exp=0 exactly on masked) + rowsum reciprocal ----
        for (int r = wid; r < BPB * NN; r += NWARPS) {
            int bb = r / NN, i = r % NN;
            float ri0 = s.rs[bb][i][0], ri1 = s.rs[bb][i][1];
            int ics = (i >= NA) ? 1 : 0;
            const float* csrow = s.cs2[ics][bb];
            int j = lane;
            float v0 = (j >= NA ? ri1 : ri0) + csrow[j] + s.base[i * NN + j];
            v0 = (v0 >= 0.f) ? v0 : 0.2f * v0;
            float e0 = __expf(v0);
            int j2 = lane + 32;
            float e1 = 0.f;
            if (j2 < NN) {
                // NOTE: NA=35 > 32, so j2 in {32,33,34} is still an aqi column -> ri0!
                float v = (j2 >= NA ? ri1 : ri0) + csrow[j2] + s.base[i * NN + j2];
                v = (v >= 0.f) ? v : 0.2f * v;
                e1 = __expf(v);
            }
            s.att[bb][i][lane] = e0;
            if (j2 < NN) s.att[bb][i][j2] = e1;
            float ss = e0 + e1;
            #pragma unroll
            for (int d = 16; d > 0; d >>= 1) ss += __shfl_xor_sync(0xffffffffu, ss, d);
            if (lane == 0) s.invs[bb][i] = 1.0f / ss;
        }
        __syncthreads();

        // ---- stage 6: outvP = (attE @ attri) * invs ----
        // R5 task map (og fastest, bb warp-constant): att reads broadcast,
        // attri reads conflict-free. Scatter to KP=33-padded outvP -> 8-way.
        for (int tt = tid; tt < BPB * 27 * 8; tt += NTHREADS) {
            int og = tt % 8;
            int ig = (tt / 8) % 27;
            int bb = tt / (27 * 8);
            int i0 = ig * 2;
            int i1 = i0 + 1;
            bool has1 = (i1 < NN);
            float4 acc0 = make_float4(0.f, 0.f, 0.f, 0.f);
            float4 acc1 = make_float4(0.f, 0.f, 0.f, 0.f);
            const float* r0 = &s.att[bb][i0][0];
            const float* r1 = &s.att[bb][has1 ? i1 : i0][0];
            const float* atrb = &s.attri[bb][0][0];
            #pragma unroll 4
            for (int j4 = 0; j4 + 4 <= NN; j4 += 4) {
                float4 a0q = *reinterpret_cast<const float4*>(&r0[j4]);
                float4 a1q = *reinterpret_cast<const float4*>(&r1[j4]);
                float4 v0 = *reinterpret_cast<const float4*>(&atrb[(j4 + 0) * HH + og * 4]);
                float4 v1 = *reinterpret_cast<const float4*>(&atrb[(j4 + 1) * HH + og * 4]);
                float4 v2 = *reinterpret_cast<const float4*>(&atrb[(j4 + 2) * HH + og * 4]);
                float4 v3 = *reinterpret_cast<const float4*>(&atrb[(j4 + 3) * HH + og * 4]);
                fma4(acc0, v0, a0q.x); fma4(acc0, v1, a0q.y);
                fma4(acc0, v2, a0q.z); fma4(acc0, v3, a0q.w);
                fma4(acc1, v0, a1q.x); fma4(acc1, v1, a1q.y);
                fma4(acc1, v2, a1q.z); fma4(acc1, v3, a1q.w);
            }
            {   // tail j = 52
                const int j = NN - 1;
                float4 v0 = *reinterpret_cast<const float4*>(&atrb[j * HH + og * 4]);
                fma4(acc0, v0, r0[j]);
                fma4(acc1, v0, r1[j]);
            }
            float inv0 = s.invs[bb][i0];
            int k0 = og * 4;
            s.outvP[i0][k0 + 0][bb] = acc0.x * inv0;
            s.outvP[i0][k0 + 1][bb] = acc0.y * inv0;
            s.outvP[i0][k0 + 2][bb] = acc0.z * inv0;
            s.outvP[i0][k0 + 3][bb] = acc0.w * inv0;
            if (has1) {
                float inv1 = s.invs[bb][i1];
                s.outvP[i1][k0 + 0][bb] = acc1.x * inv1;
                s.outvP[i1][k0 + 1][bb] = acc1.y * inv1;
                s.outvP[i1][k0 + 2][bb] = acc1.z * inv1;
                s.outvP[i1][k0 + 3][bb] = acc1.w * inv1;
            }
        }
        __syncthreads();

        // ---- stage 7: GRU (warp per node, float4 over batches) ----
        // NOTE: deterministic node<->warp mapping means hP[n][*][*] is written and
        // re-read by the SAME warp next timestep -> no barrier needed after this stage.
        for (int n = wid; n < NN; n += NWARPS) {
            bool isA = n < NA;
            const float (*Wih)[96] = isA ? s.WihA : s.WihM;
            const float (*Whh)[96] = isA ? s.WhhA : s.WhhM;
            const float* bih = isA ? s.bihA : s.bihM;
            const float* bhh = isA ? s.bhhA : s.bhhM;
            float bir = bih[lane], biz = bih[32 + lane], bin = bih[64 + lane];
            float bhr = bhh[lane], bhz = bhh[32 + lane], bhn = bhh[64 + lane];
            float4 gir = make_float4(bir, bir, bir, bir);
            float4 giz = make_float4(biz, biz, biz, biz);
            float4 gin = make_float4(bin, bin, bin, bin);
            float4 ghr = make_float4(bhr, bhr, bhr, bhr);
            float4 ghz = make_float4(bhz, bhz, bhz, bhz);
            float4 ghn = make_float4(bhn, bhn, bhn, bhn);
            float4 hold = *reinterpret_cast<const float4*>(&s.hP[n][lane][0]);
            #pragma unroll 4
            for (int k = 0; k < HH; k++) {
                float wr = Wih[k][lane], wz = Wih[k][32 + lane], wn = Wih[k][64 + lane];
                float vr = Whh[k][lane], vz = Whh[k][32 + lane], vn = Whh[k][64 + lane];
                float4 x4 = *reinterpret_cast<const float4*>(&s.outvP[n][k][0]);
                float4 h4 = *reinterpret_cast<const float4*>(&s.hP[n][k][0]);
                fma4(gir, x4, wr); fma4(giz, x4, wz); fma4(gin, x4, wn);
                fma4(ghr, h4, vr); fma4(ghz, h4, vz); fma4(ghn, h4, vn);
            }
            float4 hnew;
            {
                float r0 = sigf(gir.x + ghr.x), z0 = sigf(giz.x + ghz.x);
                hnew.x = (1.f - z0) * tanh_fast(gin.x + r0 * ghn.x) + z0 * hold.x;
                float r1 = sigf(gir.y + ghr.y), z1 = sigf(giz.y + ghz.y);
                hnew.y = (1.f - z1) * tanh_fast(gin.y + r1 * ghn.y) + z1 * hold.y;
                float r2 = sigf(gir.z + ghr.z), z2 = sigf(giz.z + ghz.z);
                hnew.z = (1.f - z2) * tanh_fast(gin.z + r2 * ghn.z) + z2 * hold.z;
                float r3 = sigf(gir.w + ghr.w), z3 = sigf(giz.w + ghz.w);
                hnew.w = (1.f - z3) * tanh_fast(gin.w + r3 * ghn.w) + z3 * hold.w;
            }
            __syncwarp();
            *reinterpret_cast<float4*>(&s.hP[n][lane][0]) = hnew;
        }
        // no __syncthreads here; next-iter stage 1 touches only in16, and the
        // barrier after stage 1 orders everything else.
    }
    __syncthreads();

    // ---- write output: h_aqi [B,35,32] then h_meo [B,18,32] ----
    for (int idx = tid; idx < BPB * NN * HH; idx += NTHREADS) {
        int o = idx & 31;
        int n = (idx >> 5) % NN;
        int bb = idx / (NN * HH);
        int b = bbase + bb;
        float v = s.hP[n][o][bb];
        if (n < NA) A.out[((size_t)b * NA + n) * HH + o] = v;
        else        A.out[(size_t)BN * NA * HH + ((size_t)b * NM + (n - NA)) * HH + o] = v;
    }
}

extern "C" void kernel_launch(void* const* d_in, const int* in_sizes, int n_in,
                              void* d_out, int out_size) {
    (void)in_sizes; (void)n_in; (void)out_size;
    const float* X_aqi = (const float*)d_in[0];
    const float* X_meo = (const float*)d_in[1];
    const float* ctx   = (const float*)d_in[2];
    const float* adj   = (const float*)d_in[3];
    const float* adjn  = (const float*)d_in[4];
    const float* e_ai  = (const float*)d_in[5];
    const float* e_amo = (const float*)d_in[6];
    const float* e_awd = (const float*)d_in[7];
    const float* e_ah  = (const float*)d_in[8];
    const float* e_mw  = (const float*)d_in[9];
    const float* e_mid = (const float*)d_in[10];
    const float* e_mmo = (const float*)d_in[11];
    const float* e_mwd = (const float*)d_in[12];
    const float* e_mh  = (const float*)d_in[13];
    const float* W_xa  = (const float*)d_in[14];
    const float* W_xm  = (const float*)d_in[15];
    const float* W_ua  = (const float*)d_in[16];
    const float* W_um  = (const float*)d_in[17];
    const float* a0    = (const float*)d_in[18];
    const float* a1    = (const float*)d_in[19];
    const float* a2    = (const float*)d_in[20];
    const float* a3    = (const float*)d_in[21];
    const float* wihA  = (const float*)d_in[22];
    const float* whhA  = (const float*)d_in[23];
    const float* bihA  = (const float*)d_in[24];
    const float* bhhA  = (const float*)d_in[25];
    const float* wihM  = (const float*)d_in[26];
    const float* whhM  = (const float*)d_in[27];
    const float* bihM  = (const float*)d_in[28];
    const float* bhhM  = (const float*)d_in[29];
    const int*   EXa   = (const int*)d_in[30];
    const int*   EXm   = (const int*)d_in[31];

    setup_kernel<<<1, 256>>>(adj, adjn, ctx, a0, a1, a2, a3);

    Args A;
    A.X_aqi = X_aqi; A.X_meo = X_meo;
    A.e_ai = e_ai; A.e_amo = e_amo; A.e_awd = e_awd; A.e_ah = e_ah;
    A.e_mw = e_mw; A.e_mid = e_mid; A.e_mmo = e_mmo; A.e_mwd = e_mwd; A.e_mh = e_mh;
    A.W_xa = W_xa; A.W_xm = W_xm; A.W_ua = W_ua; A.W_um = W_um;
    A.a0 = a0; A.a1 = a1; A.a2 = a2; A.a3 = a3;
    A.wihA = wihA; A.whhA = whhA; A.bihA = bihA; A.bhhA = bhhA;
    A.wihM = wihM; A.whhM = whhM; A.bihM = bihM; A.bhhM = bhhM;
    A.EXa = EXa; A.EXm = EXm;
    A.out = (float*)d_out;

    int smem = (int)sizeof(SmemLayout);
    cudaFuncSetAttribute(chgat_gru_kernel, cudaFuncAttributeMaxDynamicSharedMemorySize, smem);
    chgat_gru_kernel<<<BN / BPB, NTHREADS, smem>>>(A);
}

// round 13
// speedup vs baseline: 1.1383x; 1.0992x over previous
#include <cuda_runtime.h>
#include <math.h>

#define BN   1024
#define TSTEPS 48
#define NA   35
#define NM   18
#define NN   53
#define HH   32
#define CTXD 60
#define DD   92      // HH + CTXD
#define BPBMAX 4
#define NBLOCKS 296      // 2 x 148 SMs exactly: blocks 0..135 do 4 batches, 136..295 do 3
#define NB4 136          // number of 4-batch blocks (136*4 + 160*3 = 1024)
#define NTHREADS 1024
#define NWARPS (NTHREADS / 32)
#define ATTP 56      // padded att row (multiple of 4, keeps float4 alignment)
#define KP   33      // padded k-dim for outvP scatter (8-way instead of 16-way)
#define MASKED_BASE -1e13f

// ---------------- precomputed (batch/time invariant) ----------------
__device__ float g_base[NN * NN];
__device__ float g_ctx4[NN * 4];

__global__ void setup_kernel(const float* __restrict__ adj,
                             const float* __restrict__ adjn,
                             const float* __restrict__ ctx,
                             const float* __restrict__ a0,
                             const float* __restrict__ a1,
                             const float* __restrict__ a2,
                             const float* __restrict__ a3) {
    const float* A[4] = {a0, a1, a2, a3};
    for (int idx = threadIdx.x; idx < NN * NN; idx += blockDim.x) {
        int i = idx / NN, j = idx % NN;
        int bt = (i < NA ? 0 : 2) + (j < NA ? 0 : 1);
        // mask folded in: masked entries get -1e13 -> leaky -> -2e12 -> expf -> 0
        g_base[idx] = (adj[idx] > 0.0f) ? adjn[idx] * A[bt][2 * DD] : MASKED_BASE;
    }
    for (int idx = threadIdx.x; idx < NN * 4; idx += blockDim.x) {
        int n = idx >> 2, sI = idx & 3;
        int bt;
        if (sI == 0)      bt = n < NA ? 0 : 2;   // src, cols=aqi block
        else if (sI == 1) bt = n < NA ? 1 : 3;   // src, cols=meo block
        else if (sI == 2) bt = n < NA ? 0 : 1;   // dst, rows=aqi block
        else              bt = n < NA ? 2 : 3;   // dst, rows=meo block
        const float* av = A[bt] + (sI < 2 ? HH : DD + HH);
        float acc = 0.f;
        for (int c = 0; c < CTXD; c++) acc += ctx[n * CTXD + c] * av[c];
        g_ctx4[idx] = acc;
    }
}

// ---------------- main persistent kernel ----------------
struct Args {
    const float *X_aqi, *X_meo;
    const float *e_ai, *e_amo, *e_awd, *e_ah;
    const float *e_mw, *e_mid, *e_mmo, *e_mwd, *e_mh;
    const float *W_xa, *W_xm, *W_ua, *W_um;
    const float *a0, *a1, *a2, *a3;
    const float *wihA, *whhA, *bihA, *bhhA;
    const float *wihM, *whhM, *bihM, *bhhM;
    const int *EXa, *EXm;
    float *out;
};

struct SmemLayout {
    // --- float4-accessed arrays first (sizes all divisible by 16B) ---
    float hP[NN][HH][BPBMAX];       // h transposed: (node, k, batch)
    float outvP[NN][KP][BPBMAX];    // GRU input transposed, padded k
    float attri[BPBMAX][NN][HH];    // values
    float att[BPBMAX][NN][ATTP];    // RAW exp rows (unnormalized)
    float in16[BPBMAX][NN][16];     // gathered inputs (padded 16)
    float rs[BPBMAX][NN][2];
    float cs2[2][BPBMAX][NN];       // [ics][bb][j] -> conflict-free lane reads
    float invs[BPBMAX][NN];         // 1/rowsum for deferred normalization
    float Wxa[6 * HH], Wxm[4 * HH];
    float Wua16[16 * HH], Wum16[16 * HH];   // padded to 16 rows (rows 14,15 zero)
    float aS[4][HH], aD[4][HH];
    float ctx4[NN][4];
    // --- scalar-accessed arrays ---
    float base[NN * NN];
    float WihA[HH][96], WhhA[HH][96], WihM[HH][96], WhhM[HH][96];
    float bihA[96], bhhA[96], bihM[96], bhhM[96];
};

__device__ __forceinline__ float tanh_fast(float x) {
    float y;
    asm("tanh.approx.f32 %0, %1;" : "=f"(y) : "f"(x));
    return y;
}

// sigmoid via exact identity sig(x) = 0.5 + 0.5*tanh(x/2); only error source is
// tanh.approx (~2^-11), same class as the already-validated GRU tanh.
__device__ __forceinline__ float sigf(float x) {
    return fmaf(0.5f, tanh_fast(0.5f * x), 0.5f);
}

__device__ __forceinline__ void fma4(float4& a, const float4& x, float w) {
    a.x += x.x * w; a.y += x.y * w; a.z += x.z * w; a.w += x.w * w;
}

extern __shared__ __align__(16) char smem_raw[];

__global__ __launch_bounds__(NTHREADS, 1)
void chgat_gru_kernel(Args A) {
    SmemLayout& s = *reinterpret_cast<SmemLayout*>(smem_raw);
    const int tid = threadIdx.x;
    const int lane = tid & 31;
    const int wid = tid >> 5;
    const int bid = blockIdx.x;
    // mixed-size grid: first NB4 blocks handle 4 batches, rest handle 3
    const int nb = (bid < NB4) ? 4 : 3;
    const int bbase = (bid < NB4) ? 4 * bid : NB4 * 4 + 3 * (bid - NB4);

    // ---- preload weights / constants into smem ----
    for (int i = tid; i < 6 * HH; i += NTHREADS) s.Wxa[i] = A.W_xa[i];
    for (int i = tid; i < 4 * HH; i += NTHREADS) s.Wxm[i] = A.W_xm[i];
    for (int i = tid; i < 14 * HH; i += NTHREADS) { s.Wua16[i] = A.W_ua[i]; s.Wum16[i] = A.W_um[i]; }
    for (int i = tid; i < 2 * HH; i += NTHREADS) { s.Wua16[14 * HH + i] = 0.f; s.Wum16[14 * HH + i] = 0.f; }
    for (int i = tid; i < 4 * HH; i += NTHREADS) {
        int bt = i / HH, o = i % HH;
        const float* av = (bt == 0) ? A.a0 : (bt == 1) ? A.a1 : (bt == 2) ? A.a2 : A.a3;
        s.aS[bt][o] = av[o];
        s.aD[bt][o] = av[DD + o];
    }
    for (int i = tid; i < NN * 4; i += NTHREADS) (&s.ctx4[0][0])[i] = g_ctx4[i];
    for (int i = tid; i < NN * NN; i += NTHREADS) s.base[i] = g_base[i];
    for (int i = tid; i < HH * 96; i += NTHREADS) {
        int k = i / 96, g = i % 96;
        s.WihA[k][g] = A.wihA[g * HH + k];
        s.WhhA[k][g] = A.whhA[g * HH + k];
        s.WihM[k][g] = A.wihM[g * HH + k];
        s.WhhM[k][g] = A.whhM[g * HH + k];
    }
    for (int i = tid; i < 96; i += NTHREADS) {
        s.bihA[i] = A.bihA[i]; s.bhhA[i] = A.bhhA[i];
        s.bihM[i] = A.bihM[i]; s.bhhM[i] = A.bhhM[i];
    }
    for (int i = tid; i < NN * HH * BPBMAX; i += NTHREADS) (&s.hP[0][0][0])[i] = 0.f;
    __syncthreads();

    const int nNN = nb * NN;
    const int nG = nb * NN * 16;
    const int nT6 = nb * 27 * 8;

    for (int t = 0; t < TSTEPS; t++) {
        // ---- stage 1: gather in16 = [x | embeddings | 0,0] ----
        for (int idx = tid; idx < nG; idx += NTHREADS) {
            int k = idx & 15;
            int n = (idx >> 4) % NN;
            int bb = idx / (16 * NN);
            int b = bbase + bb;
            float v = 0.f;
            if (n < NA) {
                if (k < 6) {
                    v = A.X_aqi[((size_t)(b * TSTEPS + t) * NA + n) * 6 + k];
                } else if (k < 14) {
                    int p = (k - 6) >> 1, c = (k - 6) & 1;
                    int e = A.EXa[((size_t)(b * TSTEPS + t) * NA + n) * 4 + p];
                    const float* tab = (p == 0) ? A.e_ai : (p == 1) ? A.e_amo : (p == 2) ? A.e_awd : A.e_ah;
                    v = tab[e * 2 + c];
                }
            } else {
                int m = n - NA;
                if (k < 4) {
                    v = A.X_meo[((size_t)(b * TSTEPS + t) * NM + m) * 4 + k];
                } else if (k < 14) {
                    int p = (k - 4) >> 1, c = (k - 4) & 1;
                    int e = A.EXm[((size_t)(b * TSTEPS + t) * NM + m) * 5 + p];
                    const float* tab = (p == 0) ? A.e_mw : (p == 1) ? A.e_mid : (p == 2) ? A.e_mmo
                                     : (p == 3) ? A.e_mwd : A.e_mh;
                    v = tab[e * 2 + c];
                }
            }
            s.in16[bb][n][k] = v;
        }
        __syncthreads();

        // ---- stage 2: attri + 4 score dots (float4 broadcast reads of in16) ----
        for (int r = wid; r < nNN; r += NWARPS) {
            int bb = r / NN, n = r % NN;
            const float4* in4 = reinterpret_cast<const float4*>(&s.in16[bb][n][0]);
            float4 q0 = in4[0], q1 = in4[1], q2 = in4[2], q3 = in4[3];
            const int o = lane;
            float acc_a, acc_f;
            const float* Wf;
            if (n < NA) {
                acc_a = q0.x * s.Wxa[0 * HH + o] + q0.y * s.Wxa[1 * HH + o]
                      + q0.z * s.Wxa[2 * HH + o] + q0.w * s.Wxa[3 * HH + o]
                      + q1.x * s.Wxa[4 * HH + o] + q1.y * s.Wxa[5 * HH + o];
                Wf = s.Wua16;
            } else {
                acc_a = q0.x * s.Wxm[0 * HH + o] + q0.y * s.Wxm[1 * HH + o]
                      + q0.z * s.Wxm[2 * HH + o] + q0.w * s.Wxm[3 * HH + o];
                Wf = s.Wum16;
            }
            acc_f = q0.x * Wf[0 * HH + o]  + q0.y * Wf[1 * HH + o]
                  + q0.z * Wf[2 * HH + o]  + q0.w * Wf[3 * HH + o]
                  + q1.x * Wf[4 * HH + o]  + q1.y * Wf[5 * HH + o]
                  + q1.z * Wf[6 * HH + o]  + q1.w * Wf[7 * HH + o]
                  + q2.x * Wf[8 * HH + o]  + q2.y * Wf[9 * HH + o]
                  + q2.z * Wf[10 * HH + o] + q2.w * Wf[11 * HH + o]
                  + q3.x * Wf[12 * HH + o] + q3.y * Wf[13 * HH + o];
            s.attri[bb][n][o] = acc_a;
            // four score dot-products (src-aqi, src-meo, dst-aqi, dst-meo views)
            int btS0 = n < NA ? 0 : 2;
            int btS1 = n < NA ? 1 : 3;
            int btD0 = n < NA ? 0 : 1;
            int btD1 = n < NA ? 2 : 3;
            float p0 = acc_f * s.aS[btS0][o];
            float p1 = acc_f * s.aS[btS1][o];
            float p2 = acc_f * s.aD[btD0][o];
            float p3 = acc_f * s.aD[btD1][o];
            #pragma unroll
            for (int d = 16; d > 0; d >>= 1) {
                p0 += __shfl_xor_sync(0xffffffffu, p0, d);
                p1 += __shfl_xor_sync(0xffffffffu, p1, d);
                p2 += __shfl_xor_sync(0xffffffffu, p2, d);
                p3 += __shfl_xor_sync(0xffffffffu, p3, d);
            }
            if (lane == 0) {
                s.rs[bb][n][0] = p0 + s.ctx4[n][0];
                s.rs[bb][n][1] = p1 + s.ctx4[n][1];
                s.cs2[0][bb][n] = p2 + s.ctx4[n][2];
                s.cs2[1][bb][n] = p3 + s.ctx4[n][3];
            }
        }
        __syncthreads();

        // ---- stage 4+5: e row (leaky, no max — logits bounded; mask folded
        //      into base -> exp=0 exactly on masked) + rowsum reciprocal ----
        for (int r = wid; r < nNN; r += NWARPS) {
            int bb = r / NN, i = r % NN;
            float ri0 = s.rs[bb][i][0], ri1 = s.rs[bb][i][1];
            int ics = (i >= NA) ? 1 : 0;
            const float* csrow = s.cs2[ics][bb];
            int j = lane;
            float v0 = (j >= NA ? ri1 : ri0) + csrow[j] + s.base[i * NN + j];
            v0 = (v0 >= 0.f) ? v0 : 0.2f * v0;
            float e0 = __expf(v0);
            int j2 = lane + 32;
            float e1 = 0.f;
            if (j2 < NN) {
                // NOTE: NA=35 > 32, so j2 in {32,33,34} is still an aqi column -> ri0!
                float v = (j2 >= NA ? ri1 : ri0) + csrow[j2] + s.base[i * NN + j2];
                v = (v >= 0.f) ? v : 0.2f * v;
                e1 = __expf(v);
            }
            s.att[bb][i][lane] = e0;
            if (j2 < NN) s.att[bb][i][j2] = e1;
            float ss = e0 + e1;
            #pragma unroll
            for (int d = 16; d > 0; d >>= 1) ss += __shfl_xor_sync(0xffffffffu, ss, d);
            if (lane == 0) s.invs[bb][i] = 1.0f / ss;
        }
        __syncthreads();

        // ---- stage 6: outvP = (attE @ attri) * invs ----
        // R5 task map (og fastest, bb warp-constant): att reads broadcast,
        // attri reads conflict-free. Scatter to KP=33-padded outvP -> 8-way.
        for (int tt = tid; tt < nT6; tt += NTHREADS) {
            int og = tt % 8;
            int ig = (tt / 8) % 27;
            int bb = tt / (27 * 8);
            int i0 = ig * 2;
            int i1 = i0 + 1;
            bool has1 = (i1 < NN);
            float4 acc0 = make_float4(0.f, 0.f, 0.f, 0.f);
            float4 acc1 = make_float4(0.f, 0.f, 0.f, 0.f);
            const float* r0 = &s.att[bb][i0][0];
            const float* r1 = &s.att[bb][has1 ? i1 : i0][0];
            const float* atrb = &s.attri[bb][0][0];
            #pragma unroll 4
            for (int j4 = 0; j4 + 4 <= NN; j4 += 4) {
                float4 a0q = *reinterpret_cast<const float4*>(&r0[j4]);
                float4 a1q = *reinterpret_cast<const float4*>(&r1[j4]);
                float4 v0 = *reinterpret_cast<const float4*>(&atrb[(j4 + 0) * HH + og * 4]);
                float4 v1 = *reinterpret_cast<const float4*>(&atrb[(j4 + 1) * HH + og * 4]);
                float4 v2 = *reinterpret_cast<const float4*>(&atrb[(j4 + 2) * HH + og * 4]);
                float4 v3 = *reinterpret_cast<const float4*>(&atrb[(j4 + 3) * HH + og * 4]);
                fma4(acc0, v0, a0q.x); fma4(acc0, v1, a0q.y);
                fma4(acc0, v2, a0q.z); fma4(acc0, v3, a0q.w);
                fma4(acc1, v0, a1q.x); fma4(acc1, v1, a1q.y);
                fma4(acc1, v2, a1q.z); fma4(acc1, v3, a1q.w);
            }
            {   // tail j = 52
                const int j = NN - 1;
                float4 v0 = *reinterpret_cast<const float4*>(&atrb[j * HH + og * 4]);
                fma4(acc0, v0, r0[j]);
                fma4(acc1, v0, r1[j]);
            }
            float inv0 = s.invs[bb][i0];
            int k0 = og * 4;
            s.outvP[i0][k0 + 0][bb] = acc0.x * inv0;
            s.outvP[i0][k0 + 1][bb] = acc0.y * inv0;
            s.outvP[i0][k0 + 2][bb] = acc0.z * inv0;
            s.outvP[i0][k0 + 3][bb] = acc0.w * inv0;
            if (has1) {
                float inv1 = s.invs[bb][i1];
                s.outvP[i1][k0 + 0][bb] = acc1.x * inv1;
                s.outvP[i1][k0 + 1][bb] = acc1.y * inv1;
                s.outvP[i1][k0 + 2][bb] = acc1.z * inv1;
                s.outvP[i1][k0 + 3][bb] = acc1.w * inv1;
            }
        }
        __syncthreads();

        // ---- stage 7: GRU (warp per node, float4 over batches) ----
        // For nb=3 blocks, the bb=3 lane computes on garbage but writes only to
        // the unused bb=3 slot (batch lanes never mix); hP was zero-initialized.
        // NOTE: deterministic node<->warp mapping means hP[n][*][*] is written and
        // re-read by the SAME warp next timestep -> no barrier needed after this stage.
        for (int n = wid; n < NN; n += NWARPS) {
            bool isA = n < NA;
            const float (*Wih)[96] = isA ? s.WihA : s.WihM;
            const float (*Whh)[96] = isA ? s.WhhA : s.WhhM;
            const float* bih = isA ? s.bihA : s.bihM;
            const float* bhh = isA ? s.bhhA : s.bhhM;
            float bir = bih[lane], biz = bih[32 + lane], bin = bih[64 + lane];
            float bhr = bhh[lane], bhz = bhh[32 + lane], bhn = bhh[64 + lane];
            float4 gir = make_float4(bir, bir, bir, bir);
            float4 giz = make_float4(biz, biz, biz, biz);
            float4 gin = make_float4(bin, bin, bin, bin);
            float4 ghr = make_float4(bhr, bhr, bhr, bhr);
            float4 ghz = make_float4(bhz, bhz, bhz, bhz);
            float4 ghn = make_float4(bhn, bhn, bhn, bhn);
            float4 hold = *reinterpret_cast<const float4*>(&s.hP[n][lane][0]);
            #pragma unroll 4
            for (int k = 0; k < HH; k++) {
                float wr = Wih[k][lane], wz = Wih[k][32 + lane], wn = Wih[k][64 + lane];
                float vr = Whh[k][lane], vz = Whh[k][32 + lane], vn = Whh[k][64 + lane];
                float4 x4 = *reinterpret_cast<const float4*>(&s.outvP[n][k][0]);
                float4 h4 = *reinterpret_cast<const float4*>(&s.hP[n][k][0]);
                fma4(gir, x4, wr); fma4(giz, x4, wz); fma4(gin, x4, wn);
                fma4(ghr, h4, vr); fma4(ghz, h4, vz); fma4(ghn, h4, vn);
            }
            float4 hnew;
            {
                float r0 = sigf(gir.x + ghr.x), z0 = sigf(giz.x + ghz.x);
                hnew.x = (1.f - z0) * tanh_fast(gin.x + r0 * ghn.x) + z0 * hold.x;
                float r1 = sigf(gir.y + ghr.y), z1 = sigf(giz.y + ghz.y);
                hnew.y = (1.f - z1) * tanh_fast(gin.y + r1 * ghn.y) + z1 * hold.y;
                float r2 = sigf(gir.z + ghr.z), z2 = sigf(giz.z + ghz.z);
                hnew.z = (1.f - z2) * tanh_fast(gin.z + r2 * ghn.z) + z2 * hold.z;
                float r3 = sigf(gir.w + ghr.w), z3 = sigf(giz.w + ghz.w);
                hnew.w = (1.f - z3) * tanh_fast(gin.w + r3 * ghn.w) + z3 * hold.w;
            }
            __syncwarp();
            *reinterpret_cast<float4*>(&s.hP[n][lane][0]) = hnew;
        }
        // no __syncthreads here; next-iter stage 1 touches only in16, and the
        // barrier after stage 1 orders everything else.
    }
    __syncthreads();

    // ---- write output: h_aqi [B,35,32] then h_meo [B,18,32] ----
    for (int idx = tid; idx < nb * NN * HH; idx += NTHREADS) {
        int o = idx & 31;
        int n = (idx >> 5) % NN;
        int bb = idx / (NN * HH);
        int b = bbase + bb;
        float v = s.hP[n][o][bb];
        if (n < NA) A.out[((size_t)b * NA + n) * HH + o] = v;
        else        A.out[(size_t)BN * NA * HH + ((size_t)b * NM + (n - NA)) * HH + o] = v;
    }
}

extern "C" void kernel_launch(void* const* d_in, const int* in_sizes, int n_in,
                              void* d_out, int out_size) {
    (void)in_sizes; (void)n_in; (void)out_size;
    const float* X_aqi = (const float*)d_in[0];
    const float* X_meo = (const float*)d_in[1];
    const float* ctx   = (const float*)d_in[2];
    const float* adj   = (const float*)d_in[3];
    const float* adjn  = (const float*)d_in[4];
    const float* e_ai  = (const float*)d_in[5];
    const float* e_amo = (const float*)d_in[6];
    const float* e_awd = (const float*)d_in[7];
    const float* e_ah  = (const float*)d_in[8];
    const float* e_mw  = (const float*)d_in[9];
    const float* e_mid = (const float*)d_in[10];
    const float* e_mmo = (const float*)d_in[11];
    const float* e_mwd = (const float*)d_in[12];
    const float* e_mh  = (const float*)d_in[13];
    const float* W_xa  = (const float*)d_in[14];
    const float* W_xm  = (const float*)d_in[15];
    const float* W_ua  = (const float*)d_in[16];
    const float* W_um  = (const float*)d_in[17];
    const float* a0    = (const float*)d_in[18];
    const float* a1    = (const float*)d_in[19];
    const float* a2    = (const float*)d_in[20];
    const float* a3    = (const float*)d_in[21];
    const float* wihA  = (const float*)d_in[22];
    const float* whhA  = (const float*)d_in[23];
    const float* bihA  = (const float*)d_in[24];
    const float* bhhA  = (const float*)d_in[25];
    const float* wihM  = (const float*)d_in[26];
    const float* whhM  = (const float*)d_in[27];
    const float* bihM  = (const float*)d_in[28];
    const float* bhhM  = (const float*)d_in[29];
    const int*   EXa   = (const int*)d_in[30];
    const int*   EXm   = (const int*)d_in[31];

    setup_kernel<<<1, 256>>>(adj, adjn, ctx, a0, a1, a2, a3);

    Args A;
    A.X_aqi = X_aqi; A.X_meo = X_meo;
    A.e_ai = e_ai; A.e_amo = e_amo; A.e_awd = e_awd; A.e_ah = e_ah;
    A.e_mw = e_mw; A.e_mid = e_mid; A.e_mmo = e_mmo; A.e_mwd = e_mwd; A.e_mh = e_mh;
    A.W_xa = W_xa; A.W_xm = W_xm; A.W_ua = W_ua; A.W_um = W_um;
    A.a0 = a0; A.a1 = a1; A.a2 = a2; A.a3 = a3;
    A.wihA = wihA; A.whhA = whhA; A.bihA = bihA; A.bhhA = bhhA;
    A.wihM = wihM; A.whhM = whhM; A.bihM = bihM; A.bhhM = bhhM;
    A.EXa = EXa; A.EXm = EXm;
    A.out = (float*)d_out;

    int smem = (int)sizeof(SmemLayout);
    cudaFuncSetAttribute(chgat_gru_kernel, cudaFuncAttributeMaxDynamicSharedMemorySize, smem);
    chgat_gru_kernel<<<NBLOCKS, NTHREADS, smem>>>(A);
}

// round 14
// speedup vs baseline: 1.1498x; 1.0100x over previous
#include <cuda_runtime.h>
#include <math.h>

#define BN   1024
#define TSTEPS 48
#define NA   35
#define NM   18
#define NN   53
#define HH   32
#define CTXD 60
#define DD   92      // HH + CTXD
#define BPBMAX 4
#define NBLOCKS 296      // 2 x 148 SMs exactly: blocks 0..135 do 4 batches, 136..295 do 3
#define NB4 136          // number of 4-batch blocks (136*4 + 160*3 = 1024)
#define NTHREADS 1024
#define NWARPS (NTHREADS / 32)
#define ATTP 56      // padded att row (multiple of 4, keeps float4 alignment)
#define KP   33      // padded k-dim for outvP scatter (8-way instead of 16-way)
#define MASKED_BASE -1e13f

// ---------------- precomputed (batch/time invariant) ----------------
__device__ float g_base[NN * NN];
__device__ float g_ctx4[NN * 4];

__global__ void setup_kernel(const float* __restrict__ adj,
                             const float* __restrict__ adjn,
                             const float* __restrict__ ctx,
                             const float* __restrict__ a0,
                             const float* __restrict__ a1,
                             const float* __restrict__ a2,
                             const float* __restrict__ a3) {
    const float* A[4] = {a0, a1, a2, a3};
    for (int idx = threadIdx.x; idx < NN * NN; idx += blockDim.x) {
        int i = idx / NN, j = idx % NN;
        int bt = (i < NA ? 0 : 2) + (j < NA ? 0 : 1);
        // mask folded in: masked entries get -1e13 -> leaky -> -2e12 -> expf -> 0
        g_base[idx] = (adj[idx] > 0.0f) ? adjn[idx] * A[bt][2 * DD] : MASKED_BASE;
    }
    for (int idx = threadIdx.x; idx < NN * 4; idx += blockDim.x) {
        int n = idx >> 2, sI = idx & 3;
        int bt;
        if (sI == 0)      bt = n < NA ? 0 : 2;   // src, cols=aqi block
        else if (sI == 1) bt = n < NA ? 1 : 3;   // src, cols=meo block
        else if (sI == 2) bt = n < NA ? 0 : 1;   // dst, rows=aqi block
        else              bt = n < NA ? 2 : 3;   // dst, rows=meo block
        const float* av = A[bt] + (sI < 2 ? HH : DD + HH);
        float acc = 0.f;
        for (int c = 0; c < CTXD; c++) acc += ctx[n * CTXD + c] * av[c];
        g_ctx4[idx] = acc;
    }
}

// ---------------- main persistent kernel ----------------
struct Args {
    const float *X_aqi, *X_meo;
    const float *e_ai, *e_amo, *e_awd, *e_ah;
    const float *e_mw, *e_mid, *e_mmo, *e_mwd, *e_mh;
    const float *W_xa, *W_xm, *W_ua, *W_um;
    const float *a0, *a1, *a2, *a3;
    const float *wihA, *whhA, *bihA, *bhhA;
    const float *wihM, *whhM, *bihM, *bhhM;
    const int *EXa, *EXm;
    float *out;
};

struct SmemLayout {
    // --- float4-accessed arrays first (sizes all divisible by 16B) ---
    float hP[NN][HH][BPBMAX];       // h transposed: (node, k, batch)
    float outvP[NN][KP][BPBMAX];    // GRU input transposed, padded k
    float attri[BPBMAX][NN][HH];    // values
    float att[BPBMAX][NN][ATTP];    // RAW exp rows (unnormalized)
    float in16[BPBMAX][NN][16];     // gathered inputs (padded 16)
    float rs[BPBMAX][NN][2];
    float cs2[2][BPBMAX][NN];       // [ics][bb][j] -> conflict-free lane reads
    float invs[BPBMAX][NN];         // 1/rowsum for deferred normalization
    float Wxa[6 * HH], Wxm[4 * HH];
    float Wua16[16 * HH], Wum16[16 * HH];   // padded to 16 rows (rows 14,15 zero)
    float aS[4][HH], aD[4][HH];
    float ctx4[NN][4];
    // --- scalar-accessed arrays ---
    float base[NN * NN];
    float WihA[HH][96], WhhA[HH][96], WihM[HH][96], WhhM[HH][96];
    float bihA[96], bhhA[96], bihM[96], bhhM[96];
};

__device__ __forceinline__ float tanh_fast(float x) {
    float y;
    asm("tanh.approx.f32 %0, %1;" : "=f"(y) : "f"(x));
    return y;
}

// sigmoid via exact identity sig(x) = 0.5 + 0.5*tanh(x/2); only error source is
// tanh.approx (~2^-11), same class as the already-validated GRU tanh.
__device__ __forceinline__ float sigf(float x) {
    return fmaf(0.5f, tanh_fast(0.5f * x), 0.5f);
}

__device__ __forceinline__ void fma4(float4& a, const float4& x, float w) {
    a.x += x.x * w; a.y += x.y * w; a.z += x.z * w; a.w += x.w * w;
}

extern __shared__ __align__(16) char smem_raw[];

__global__ __launch_bounds__(NTHREADS, 1)
void chgat_gru_kernel(Args A) {
    SmemLayout& s = *reinterpret_cast<SmemLayout*>(smem_raw);
    const int tid = threadIdx.x;
    const int lane = tid & 31;
    const int wid = tid >> 5;
    const int bid = blockIdx.x;
    // mixed-size grid: first NB4 blocks handle 4 batches, rest handle 3
    const int nb = (bid < NB4) ? 4 : 3;
    const int bbase = (bid < NB4) ? 4 * bid : NB4 * 4 + 3 * (bid - NB4);

    // ---- preload weights / constants into smem ----
    for (int i = tid; i < 6 * HH; i += NTHREADS) s.Wxa[i] = A.W_xa[i];
    for (int i = tid; i < 4 * HH; i += NTHREADS) s.Wxm[i] = A.W_xm[i];
    for (int i = tid; i < 14 * HH; i += NTHREADS) { s.Wua16[i] = A.W_ua[i]; s.Wum16[i] = A.W_um[i]; }
    for (int i = tid; i < 2 * HH; i += NTHREADS) { s.Wua16[14 * HH + i] = 0.f; s.Wum16[14 * HH + i] = 0.f; }
    for (int i = tid; i < 4 * HH; i += NTHREADS) {
        int bt = i / HH, o = i % HH;
        const float* av = (bt == 0) ? A.a0 : (bt == 1) ? A.a1 : (bt == 2) ? A.a2 : A.a3;
        s.aS[bt][o] = av[o];
        s.aD[bt][o] = av[DD + o];
    }
    for (int i = tid; i < NN * 4; i += NTHREADS) (&s.ctx4[0][0])[i] = g_ctx4[i];
    for (int i = tid; i < NN * NN; i += NTHREADS) s.base[i] = g_base[i];
    for (int i = tid; i < HH * 96; i += NTHREADS) {
        int k = i / 96, g = i % 96;
        s.WihA[k][g] = A.wihA[g * HH + k];
        s.WhhA[k][g] = A.whhA[g * HH + k];
        s.WihM[k][g] = A.wihM[g * HH + k];
        s.WhhM[k][g] = A.whhM[g * HH + k];
    }
    for (int i = tid; i < 96; i += NTHREADS) {
        s.bihA[i] = A.bihA[i]; s.bhhA[i] = A.bhhA[i];
        s.bihM[i] = A.bihM[i]; s.bhhM[i] = A.bhhM[i];
    }
    for (int i = tid; i < NN * HH * BPBMAX; i += NTHREADS) (&s.hP[0][0][0])[i] = 0.f;
    __syncthreads();

    const int nNN = nb * NN;
    const int nG = nb * NN * 16;
    const int nT6 = nb * 27 * 8;

    for (int t = 0; t < TSTEPS; t++) {
        // ---- stage 1: gather in16 = [x | embeddings | 0,0] ----
        for (int idx = tid; idx < nG; idx += NTHREADS) {
            int k = idx & 15;
            int n = (idx >> 4) % NN;
            int bb = idx / (16 * NN);
            int b = bbase + bb;
            float v = 0.f;
            if (n < NA) {
                if (k < 6) {
                    v = A.X_aqi[((size_t)(b * TSTEPS + t) * NA + n) * 6 + k];
                } else if (k < 14) {
                    int p = (k - 6) >> 1, c = (k - 6) & 1;
                    int e = A.EXa[((size_t)(b * TSTEPS + t) * NA + n) * 4 + p];
                    const float* tab = (p == 0) ? A.e_ai : (p == 1) ? A.e_amo : (p == 2) ? A.e_awd : A.e_ah;
                    v = tab[e * 2 + c];
                }
            } else {
                int m = n - NA;
                if (k < 4) {
                    v = A.X_meo[((size_t)(b * TSTEPS + t) * NM + m) * 4 + k];
                } else if (k < 14) {
                    int p = (k - 4) >> 1, c = (k - 4) & 1;
                    int e = A.EXm[((size_t)(b * TSTEPS + t) * NM + m) * 5 + p];
                    const float* tab = (p == 0) ? A.e_mw : (p == 1) ? A.e_mid : (p == 2) ? A.e_mmo
                                     : (p == 3) ? A.e_mwd : A.e_mh;
                    v = tab[e * 2 + c];
                }
            }
            s.in16[bb][n][k] = v;
        }
        __syncthreads();

        // ---- stage 2: attri + 4 score dots (float4 broadcast reads of in16) ----
        for (int r = wid; r < nNN; r += NWARPS) {
            int bb = r / NN, n = r % NN;
            const float4* in4 = reinterpret_cast<const float4*>(&s.in16[bb][n][0]);
            float4 q0 = in4[0], q1 = in4[1], q2 = in4[2], q3 = in4[3];
            const int o = lane;
            float acc_a, acc_f;
            const float* Wf;
            if (n < NA) {
                acc_a = q0.x * s.Wxa[0 * HH + o] + q0.y * s.Wxa[1 * HH + o]
                      + q0.z * s.Wxa[2 * HH + o] + q0.w * s.Wxa[3 * HH + o]
                      + q1.x * s.Wxa[4 * HH + o] + q1.y * s.Wxa[5 * HH + o];
                Wf = s.Wua16;
            } else {
                acc_a = q0.x * s.Wxm[0 * HH + o] + q0.y * s.Wxm[1 * HH + o]
                      + q0.z * s.Wxm[2 * HH + o] + q0.w * s.Wxm[3 * HH + o];
                Wf = s.Wum16;
            }
            acc_f = q0.x * Wf[0 * HH + o]  + q0.y * Wf[1 * HH + o]
                  + q0.z * Wf[2 * HH + o]  + q0.w * Wf[3 * HH + o]
                  + q1.x * Wf[4 * HH + o]  + q1.y * Wf[5 * HH + o]
                  + q1.z * Wf[6 * HH + o]  + q1.w * Wf[7 * HH + o]
                  + q2.x * Wf[8 * HH + o]  + q2.y * Wf[9 * HH + o]
                  + q2.z * Wf[10 * HH + o] + q2.w * Wf[11 * HH + o]
                  + q3.x * Wf[12 * HH + o] + q3.y * Wf[13 * HH + o];
            s.attri[bb][n][o] = acc_a;
            // four score dot-products (src-aqi, src-meo, dst-aqi, dst-meo views)
            int btS0 = n < NA ? 0 : 2;
            int btS1 = n < NA ? 1 : 3;
            int btD0 = n < NA ? 0 : 1;
            int btD1 = n < NA ? 2 : 3;
            float p0 = acc_f * s.aS[btS0][o];
            float p1 = acc_f * s.aS[btS1][o];
            float p2 = acc_f * s.aD[btD0][o];
            float p3 = acc_f * s.aD[btD1][o];
            #pragma unroll
            for (int d = 16; d > 0; d >>= 1) {
                p0 += __shfl_xor_sync(0xffffffffu, p0, d);
                p1 += __shfl_xor_sync(0xffffffffu, p1, d);
                p2 += __shfl_xor_sync(0xffffffffu, p2, d);
                p3 += __shfl_xor_sync(0xffffffffu, p3, d);
            }
            if (lane == 0) {
                s.rs[bb][n][0] = p0 + s.ctx4[n][0];
                s.rs[bb][n][1] = p1 + s.ctx4[n][1];
                s.cs2[0][bb][n] = p2 + s.ctx4[n][2];
                s.cs2[1][bb][n] = p3 + s.ctx4[n][3];
            }
        }
        __syncthreads();

        // ---- stage 4+5: e row (leaky, no max — logits bounded; mask folded
        //      into base -> exp=0 exactly on masked) + rowsum reciprocal ----
        for (int r = wid; r < nNN; r += NWARPS) {
            int bb = r / NN, i = r % NN;
            float ri0 = s.rs[bb][i][0], ri1 = s.rs[bb][i][1];
            int ics = (i >= NA) ? 1 : 0;
            const float* csrow = s.cs2[ics][bb];
            int j = lane;
            float v0 = (j >= NA ? ri1 : ri0) + csrow[j] + s.base[i * NN + j];
            v0 = (v0 >= 0.f) ? v0 : 0.2f * v0;
            float e0 = __expf(v0);
            int j2 = lane + 32;
            float e1 = 0.f;
            if (j2 < NN) {
                // NOTE: NA=35 > 32, so j2 in {32,33,34} is still an aqi column -> ri0!
                float v = (j2 >= NA ? ri1 : ri0) + csrow[j2] + s.base[i * NN + j2];
                v = (v >= 0.f) ? v : 0.2f * v;
                e1 = __expf(v);
            }
            s.att[bb][i][lane] = e0;
            if (j2 < NN) s.att[bb][i][j2] = e1;
            float ss = e0 + e1;
            #pragma unroll
            for (int d = 16; d > 0; d >>= 1) ss += __shfl_xor_sync(0xffffffffu, ss, d);
            if (lane == 0) s.invs[bb][i] = 1.0f / ss;
        }
        __syncthreads();

        // ---- stage 6: outvP = (attE @ attri) * invs ----
        // R5 task map (og fastest, bb warp-constant): att reads broadcast,
        // attri reads conflict-free. Scatter to KP=33-padded outvP -> 8-way.
        for (int tt = tid; tt < nT6; tt += NTHREADS) {
            int og = tt % 8;
            int ig = (tt / 8) % 27;
            int bb = tt / (27 * 8);
            int i0 = ig * 2;
            int i1 = i0 + 1;
            bool has1 = (i1 < NN);
            float4 acc0 = make_float4(0.f, 0.f, 0.f, 0.f);
            float4 acc1 = make_float4(0.f, 0.f, 0.f, 0.f);
            const float* r0 = &s.att[bb][i0][0];
            const float* r1 = &s.att[bb][has1 ? i1 : i0][0];
            const float* atrb = &s.attri[bb][0][0];
            #pragma unroll 4
            for (int j4 = 0; j4 + 4 <= NN; j4 += 4) {
                float4 a0q = *reinterpret_cast<const float4*>(&r0[j4]);
                float4 a1q = *reinterpret_cast<const float4*>(&r1[j4]);
                float4 v0 = *reinterpret_cast<const float4*>(&atrb[(j4 + 0) * HH + og * 4]);
                float4 v1 = *reinterpret_cast<const float4*>(&atrb[(j4 + 1) * HH + og * 4]);
                float4 v2 = *reinterpret_cast<const float4*>(&atrb[(j4 + 2) * HH + og * 4]);
                float4 v3 = *reinterpret_cast<const float4*>(&atrb[(j4 + 3) * HH + og * 4]);
                fma4(acc0, v0, a0q.x); fma4(acc0, v1, a0q.y);
                fma4(acc0, v2, a0q.z); fma4(acc0, v3, a0q.w);
                fma4(acc1, v0, a1q.x); fma4(acc1, v1, a1q.y);
                fma4(acc1, v2, a1q.z); fma4(acc1, v3, a1q.w);
            }
            {   // tail j = 52
                const int j = NN - 1;
                float4 v0 = *reinterpret_cast<const float4*>(&atrb[j * HH + og * 4]);
                fma4(acc0, v0, r0[j]);
                fma4(acc1, v0, r1[j]);
            }
            float inv0 = s.invs[bb][i0];
            int k0 = og * 4;
            s.outvP[i0][k0 + 0][bb] = acc0.x * inv0;
            s.outvP[i0][k0 + 1][bb] = acc0.y * inv0;
            s.outvP[i0][k0 + 2][bb] = acc0.z * inv0;
            s.outvP[i0][k0 + 3][bb] = acc0.w * inv0;
            if (has1) {
                float inv1 = s.invs[bb][i1];
                s.outvP[i1][k0 + 0][bb] = acc1.x * inv1;
                s.outvP[i1][k0 + 1][bb] = acc1.y * inv1;
                s.outvP[i1][k0 + 2][bb] = acc1.z * inv1;
                s.outvP[i1][k0 + 3][bb] = acc1.w * inv1;
            }
        }
        __syncthreads();

        // ---- stage 7: GRU, 2 same-type nodes per warp (weight reads amortized),
        //      fused r/z accumulators; 27 tasks in one round. For nb=3 blocks the
        //      bb=3 lane computes garbage confined to its own unused slot.
        //      NOTE: deterministic task<->warp map: hP rows written and re-read by
        //      the SAME warp next timestep -> no barrier after. Warps 27..31 and
        //      early finishers run ahead into next-t stage-1 LDGs.
        if (wid < 27) {
            int n0, n1; bool has2, isA;
            if (wid < 17)       { n0 = 2 * wid;              n1 = n0 + 1; has2 = true;  isA = true;  }
            else if (wid == 17) { n0 = 34;                   n1 = 34;     has2 = false; isA = true;  }
            else                { n0 = 35 + 2 * (wid - 18);  n1 = n0 + 1; has2 = true;  isA = false; }
            const float (*Wih)[96] = isA ? s.WihA : s.WihM;
            const float (*Whh)[96] = isA ? s.WhhA : s.WhhM;
            const float* bih = isA ? s.bihA : s.bihM;
            const float* bhh = isA ? s.bhhA : s.bhhM;
            float br  = bih[lane]      + bhh[lane];
            float bz  = bih[32 + lane] + bhh[32 + lane];
            float bi_n = bih[64 + lane];
            float bh_n = bhh[64 + lane];
            float4 gr0 = make_float4(br, br, br, br);
            float4 gz0 = make_float4(bz, bz, bz, bz);
            float4 gin0 = make_float4(bi_n, bi_n, bi_n, bi_n);
            float4 ghn0 = make_float4(bh_n, bh_n, bh_n, bh_n);
            float4 gr1 = gr0, gz1 = gz0, gin1 = gin0, ghn1 = ghn0;
            #pragma unroll 4
            for (int k = 0; k < HH; k++) {
                float wr = Wih[k][lane], wz = Wih[k][32 + lane], wn = Wih[k][64 + lane];
                float vr = Whh[k][lane], vz = Whh[k][32 + lane], vn = Whh[k][64 + lane];
                float4 x0 = *reinterpret_cast<const float4*>(&s.outvP[n0][k][0]);
                float4 h0 = *reinterpret_cast<const float4*>(&s.hP[n0][k][0]);
                fma4(gr0, x0, wr);  fma4(gr0, h0, vr);
                fma4(gz0, x0, wz);  fma4(gz0, h0, vz);
                fma4(gin0, x0, wn); fma4(ghn0, h0, vn);
                float4 x1 = *reinterpret_cast<const float4*>(&s.outvP[n1][k][0]);
                float4 h1 = *reinterpret_cast<const float4*>(&s.hP[n1][k][0]);
                fma4(gr1, x1, wr);  fma4(gr1, h1, vr);
                fma4(gz1, x1, wz);  fma4(gz1, h1, vz);
                fma4(gin1, x1, wn); fma4(ghn1, h1, vn);
            }
            float4 hold0 = *reinterpret_cast<const float4*>(&s.hP[n0][lane][0]);
            float4 hold1 = *reinterpret_cast<const float4*>(&s.hP[n1][lane][0]);
            float4 hnew0, hnew1;
            {
                float r, z;
                r = sigf(gr0.x); z = sigf(gz0.x);
                hnew0.x = (1.f - z) * tanh_fast(gin0.x + r * ghn0.x) + z * hold0.x;
                r = sigf(gr0.y); z = sigf(gz0.y);
                hnew0.y = (1.f - z) * tanh_fast(gin0.y + r * ghn0.y) + z * hold0.y;
                r = sigf(gr0.z); z = sigf(gz0.z);
                hnew0.z = (1.f - z) * tanh_fast(gin0.z + r * ghn0.z) + z * hold0.z;
                r = sigf(gr0.w); z = sigf(gz0.w);
                hnew0.w = (1.f - z) * tanh_fast(gin0.w + r * ghn0.w) + z * hold0.w;
                r = sigf(gr1.x); z = sigf(gz1.x);
                hnew1.x = (1.f - z) * tanh_fast(gin1.x + r * ghn1.x) + z * hold1.x;
                r = sigf(gr1.y); z = sigf(gz1.y);
                hnew1.y = (1.f - z) * tanh_fast(gin1.y + r * ghn1.y) + z * hold1.y;
                r = sigf(gr1.z); z = sigf(gz1.z);
                hnew1.z = (1.f - z) * tanh_fast(gin1.z + r * ghn1.z) + z * hold1.z;
                r = sigf(gr1.w); z = sigf(gz1.w);
                hnew1.w = (1.f - z) * tanh_fast(gin1.w + r * ghn1.w) + z * hold1.w;
            }
            __syncwarp();   // all lanes done reading hP rows n0/n1 before any write
            *reinterpret_cast<float4*>(&s.hP[n0][lane][0]) = hnew0;
            if (has2) *reinterpret_cast<float4*>(&s.hP[n1][lane][0]) = hnew1;
        }
        // no __syncthreads here; next-iter stage 1 touches only in16, and the
        // barrier after stage 1 orders everything else.
    }
    __syncthreads();

    // ---- write output: h_aqi [B,35,32] then h_meo [B,18,32] ----
    for (int idx = tid; idx < nb * NN * HH; idx += NTHREADS) {
        int o = idx & 31;
        int n = (idx >> 5) % NN;
        int bb = idx / (NN * HH);
        int b = bbase + bb;
        float v = s.hP[n][o][bb];
        if (n < NA) A.out[((size_t)b * NA + n) * HH + o] = v;
        else        A.out[(size_t)BN * NA * HH + ((size_t)b * NM + (n - NA)) * HH + o] = v;
    }
}

extern "C" void kernel_launch(void* const* d_in, const int* in_sizes, int n_in,
                              void* d_out, int out_size) {
    (void)in_sizes; (void)n_in; (void)out_size;
    const float* X_aqi = (const float*)d_in[0];
    const float* X_meo = (const float*)d_in[1];
    const float* ctx   = (const float*)d_in[2];
    const float* adj   = (const float*)d_in[3];
    const float* adjn  = (const float*)d_in[4];
    const float* e_ai  = (const float*)d_in[5];
    const float* e_amo = (const float*)d_in[6];
    const float* e_awd = (const float*)d_in[7];
    const float* e_ah  = (const float*)d_in[8];
    const float* e_mw  = (const float*)d_in[9];
    const float* e_mid = (const float*)d_in[10];
    const float* e_mmo = (const float*)d_in[11];
    const float* e_mwd = (const float*)d_in[12];
    const float* e_mh  = (const float*)d_in[13];
    const float* W_xa  = (const float*)d_in[14];
    const float* W_xm  = (const float*)d_in[15];
    const float* W_ua  = (const float*)d_in[16];
    const float* W_um  = (const float*)d_in[17];
    const float* a0    = (const float*)d_in[18];
    const float* a1    = (const float*)d_in[19];
    const float* a2    = (const float*)d_in[20];
    const float* a3    = (const float*)d_in[21];
    const float* wihA  = (const float*)d_in[22];
    const float* whhA  = (const float*)d_in[23];
    const float* bihA  = (const float*)d_in[24];
    const float* bhhA  = (const float*)d_in[25];
    const float* wihM  = (const float*)d_in[26];
    const float* whhM  = (const float*)d_in[27];
    const float* bihM  = (const float*)d_in[28];
    const float* bhhM  = (const float*)d_in[29];
    const int*   EXa   = (const int*)d_in[30];
    const int*   EXm   = (const int*)d_in[31];

    setup_kernel<<<1, 256>>>(adj, adjn, ctx, a0, a1, a2, a3);

    Args A;
    A.X_aqi = X_aqi; A.X_meo = X_meo;
    A.e_ai = e_ai; A.e_amo = e_amo; A.e_awd = e_awd; A.e_ah = e_ah;
    A.e_mw = e_mw; A.e_mid = e_mid; A.e_mmo = e_mmo; A.e_mwd = e_mwd; A.e_mh = e_mh;
    A.W_xa = W_xa; A.W_xm = W_xm; A.W_ua = W_ua; A.W_um = W_um;
    A.a0 = a0; A.a1 = a1; A.a2 = a2; A.a3 = a3;
    A.wihA = wihA; A.whhA = whhA; A.bihA = bihA; A.bhhA = bhhA;
    A.wihM = wihM; A.whhM = whhM; A.bihM = bihM; A.bhhM = bhhM;
    A.EXa = EXa; A.EXm = EXm;
    A.out = (float*)d_out;

    int smem = (int)sizeof(SmemLayout);
    cudaFuncSetAttribute(chgat_gru_kernel, cudaFuncAttributeMaxDynamicSharedMemorySize, smem);
    chgat_gru_kernel<<<NBLOCKS, NTHREADS, smem>>>(A);
}

// round 15
// speedup vs baseline: 1.2346x; 1.0738x over previous
#include <cuda_runtime.h>
#include <math.h>

#define BN   1024
#define TSTEPS 48
#define NA   35
#define NM   18
#define NN   53
#define HH   32
#define CTXD 60
#define DD   92      // HH + CTXD
#define BPBMAX 4
#define NBLOCKS 296      // 2 x 148 SMs exactly: blocks 0..135 do 4 batches, 136..295 do 3
#define NB4 136          // number of 4-batch blocks (136*4 + 160*3 = 1024)
#define NTHREADS 1024
#define NWARPS (NTHREADS / 32)
#define ATTP 56      // padded att row (multiple of 4, keeps float4 alignment)
#define KP   33      // padded k-dim for outvP scatter (8-way instead of 16-way)
#define MASKED_BASE -1e13f

// ---------------- precomputed (batch/time invariant) ----------------
__device__ float g_base[NN * NN];
__device__ float g_ctx4[NN * 4];

__global__ void setup_kernel(const float* __restrict__ adj,
                             const float* __restrict__ adjn,
                             const float* __restrict__ ctx,
                             const float* __restrict__ a0,
                             const float* __restrict__ a1,
                             const float* __restrict__ a2,
                             const float* __restrict__ a3) {
    const float* A[4] = {a0, a1, a2, a3};
    for (int idx = threadIdx.x; idx < NN * NN; idx += blockDim.x) {
        int i = idx / NN, j = idx % NN;
        int bt = (i < NA ? 0 : 2) + (j < NA ? 0 : 1);
        // mask folded in: masked entries get -1e13 -> leaky -> -2e12 -> expf -> 0
        g_base[idx] = (adj[idx] > 0.0f) ? adjn[idx] * A[bt][2 * DD] : MASKED_BASE;
    }
    for (int idx = threadIdx.x; idx < NN * 4; idx += blockDim.x) {
        int n = idx >> 2, sI = idx & 3;
        int bt;
        if (sI == 0)      bt = n < NA ? 0 : 2;   // src, cols=aqi block
        else if (sI == 1) bt = n < NA ? 1 : 3;   // src, cols=meo block
        else if (sI == 2) bt = n < NA ? 0 : 1;   // dst, rows=aqi block
        else              bt = n < NA ? 2 : 3;   // dst, rows=meo block
        const float* av = A[bt] + (sI < 2 ? HH : DD + HH);
        float acc = 0.f;
        for (int c = 0; c < CTXD; c++) acc += ctx[n * CTXD + c] * av[c];
        g_ctx4[idx] = acc;
    }
}

// ---------------- main persistent kernel ----------------
struct Args {
    const float *X_aqi, *X_meo;
    const float *e_ai, *e_amo, *e_awd, *e_ah;
    const float *e_mw, *e_mid, *e_mmo, *e_mwd, *e_mh;
    const float *W_xa, *W_xm, *W_ua, *W_um;
    const float *a0, *a1, *a2, *a3;
    const float *wihA, *whhA, *bihA, *bhhA;
    const float *wihM, *whhM, *bihM, *bhhM;
    const int *EXa, *EXm;
    float *out;
};

struct SmemLayout {
    // --- float4-accessed arrays first (sizes all divisible by 16B) ---
    float hP[NN][HH][BPBMAX];       // h transposed: (node, k, batch)
    float outvP[NN][KP][BPBMAX];    // GRU input transposed, padded k
    float attri[BPBMAX][NN][HH];    // values
    float att[BPBMAX][NN][ATTP];    // RAW exp rows (unnormalized)
    float in16[BPBMAX][NN][16];     // gathered inputs (padded 16)
    float rs[BPBMAX][NN][2];
    float cs2[2][BPBMAX][NN];       // [ics][bb][j] -> conflict-free lane reads
    float invs[BPBMAX][NN];         // 1/rowsum for deferred normalization
    float Wxa[6 * HH], Wxm[4 * HH];
    float Wua16[16 * HH], Wum16[16 * HH];   // padded to 16 rows (rows 14,15 zero)
    float aS[4][HH], aD[4][HH];
    float ctx4[NN][4];
    // --- scalar-accessed arrays ---
    float base[NN * NN];
    float WihA[HH][96], WhhA[HH][96], WihM[HH][96], WhhM[HH][96];
    float bihA[96], bhhA[96], bihM[96], bhhM[96];
};

__device__ __forceinline__ float tanh_fast(float x) {
    float y;
    asm("tanh.approx.f32 %0, %1;" : "=f"(y) : "f"(x));
    return y;
}

// sigmoid via exact identity sig(x) = 0.5 + 0.5*tanh(x/2); only error source is
// tanh.approx (~2^-11), same class as the already-validated GRU tanh.
__device__ __forceinline__ float sigf(float x) {
    return fmaf(0.5f, tanh_fast(0.5f * x), 0.5f);
}

__device__ __forceinline__ void fma4(float4& a, const float4& x, float w) {
    a.x += x.x * w; a.y += x.y * w; a.z += x.z * w; a.w += x.w * w;
}

extern __shared__ __align__(16) char smem_raw[];

__global__ __launch_bounds__(NTHREADS, 1)
void chgat_gru_kernel(Args A) {
    SmemLayout& s = *reinterpret_cast<SmemLayout*>(smem_raw);
    const int tid = threadIdx.x;
    const int lane = tid & 31;
    const int wid = tid >> 5;
    const int bid = blockIdx.x;
    // mixed-size grid: first NB4 blocks handle 4 batches, rest handle 3
    const int nb = (bid < NB4) ? 4 : 3;
    const int bbase = (bid < NB4) ? 4 * bid : NB4 * 4 + 3 * (bid - NB4);

    // ---- preload weights / constants into smem ----
    for (int i = tid; i < 6 * HH; i += NTHREADS) s.Wxa[i] = A.W_xa[i];
    for (int i = tid; i < 4 * HH; i += NTHREADS) s.Wxm[i] = A.W_xm[i];
    for (int i = tid; i < 14 * HH; i += NTHREADS) { s.Wua16[i] = A.W_ua[i]; s.Wum16[i] = A.W_um[i]; }
    for (int i = tid; i < 2 * HH; i += NTHREADS) { s.Wua16[14 * HH + i] = 0.f; s.Wum16[14 * HH + i] = 0.f; }
    for (int i = tid; i < 4 * HH; i += NTHREADS) {
        int bt = i / HH, o = i % HH;
        const float* av = (bt == 0) ? A.a0 : (bt == 1) ? A.a1 : (bt == 2) ? A.a2 : A.a3;
        s.aS[bt][o] = av[o];
        s.aD[bt][o] = av[DD + o];
    }
    for (int i = tid; i < NN * 4; i += NTHREADS) (&s.ctx4[0][0])[i] = g_ctx4[i];
    for (int i = tid; i < NN * NN; i += NTHREADS) s.base[i] = g_base[i];
    for (int i = tid; i < HH * 96; i += NTHREADS) {
        int k = i / 96, g = i % 96;
        s.WihA[k][g] = A.wihA[g * HH + k];
        s.WhhA[k][g] = A.whhA[g * HH + k];
        s.WihM[k][g] = A.wihM[g * HH + k];
        s.WhhM[k][g] = A.whhM[g * HH + k];
    }
    for (int i = tid; i < 96; i += NTHREADS) {
        s.bihA[i] = A.bihA[i]; s.bhhA[i] = A.bhhA[i];
        s.bihM[i] = A.bihM[i]; s.bhhM[i] = A.bhhM[i];
    }
    for (int i = tid; i < NN * HH * BPBMAX; i += NTHREADS) (&s.hP[0][0][0])[i] = 0.f;
    __syncthreads();

    const int nNN = nb * NN;
    const int nG = nb * NN * 16;
    const int nT6 = nb * 27 * 8;

    for (int t = 0; t < TSTEPS; t++) {
        // ---- stage 1: gather in16 = [x | embeddings | 0,0] ----
        for (int idx = tid; idx < nG; idx += NTHREADS) {
            int k = idx & 15;
            int n = (idx >> 4) % NN;
            int bb = idx / (16 * NN);
            int b = bbase + bb;
            float v = 0.f;
            if (n < NA) {
                if (k < 6) {
                    v = A.X_aqi[((size_t)(b * TSTEPS + t) * NA + n) * 6 + k];
                } else if (k < 14) {
                    int p = (k - 6) >> 1, c = (k - 6) & 1;
                    int e = A.EXa[((size_t)(b * TSTEPS + t) * NA + n) * 4 + p];
                    const float* tab = (p == 0) ? A.e_ai : (p == 1) ? A.e_amo : (p == 2) ? A.e_awd : A.e_ah;
                    v = tab[e * 2 + c];
                }
            } else {
                int m = n - NA;
                if (k < 4) {
                    v = A.X_meo[((size_t)(b * TSTEPS + t) * NM + m) * 4 + k];
                } else if (k < 14) {
                    int p = (k - 4) >> 1, c = (k - 4) & 1;
                    int e = A.EXm[((size_t)(b * TSTEPS + t) * NM + m) * 5 + p];
                    const float* tab = (p == 0) ? A.e_mw : (p == 1) ? A.e_mid : (p == 2) ? A.e_mmo
                                     : (p == 3) ? A.e_mwd : A.e_mh;
                    v = tab[e * 2 + c];
                }
            }
            s.in16[bb][n][k] = v;
        }
        __syncthreads();

        // ---- stage 2: attri + 4 score dots; 2 same-type nodes per warp,
        //      weights hoisted to registers (amortized over 8 (node,batch) units).
        //      Unconditional bb<4 sweep: for nb=3 blocks the bb=3 unit reads
        //      uninitialized in16[3] and writes only to unused rs/cs2/attri slots
        //      (never read by stages 4-6, which loop bb<nb) — same garbage-
        //      confinement argument as stage 7 (validated R13/14). ----
        if (wid < 27) {
            int n0, n1; bool has2, isA;
            if (wid < 17)       { n0 = 2 * wid;              n1 = n0 + 1; has2 = true;  isA = true;  }
            else if (wid == 17) { n0 = 34;                   n1 = 34;     has2 = false; isA = true;  }
            else                { n0 = 35 + 2 * (wid - 18);  n1 = n0 + 1; has2 = true;  isA = false; }
            const int o = lane;
            const float* Wa = isA ? s.Wxa : s.Wxm;
            const float* Wf = isA ? s.Wua16 : s.Wum16;
            float wa0 = Wa[0 * HH + o], wa1 = Wa[1 * HH + o];
            float wa2 = Wa[2 * HH + o], wa3 = Wa[3 * HH + o];
            float wa4 = isA ? Wa[4 * HH + o] : 0.f;
            float wa5 = isA ? Wa[5 * HH + o] : 0.f;
            float f0 = Wf[0 * HH + o],  f1 = Wf[1 * HH + o],  f2 = Wf[2 * HH + o];
            float f3 = Wf[3 * HH + o],  f4 = Wf[4 * HH + o],  f5 = Wf[5 * HH + o];
            float f6 = Wf[6 * HH + o],  f7 = Wf[7 * HH + o],  f8 = Wf[8 * HH + o];
            float f9 = Wf[9 * HH + o],  f10 = Wf[10 * HH + o], f11 = Wf[11 * HH + o];
            float f12 = Wf[12 * HH + o], f13 = Wf[13 * HH + o];
            int btS0 = isA ? 0 : 2;
            int btS1 = isA ? 1 : 3;
            int btD0 = isA ? 0 : 1;
            int btD1 = isA ? 2 : 3;
            float as0 = s.aS[btS0][o], as1 = s.aS[btS1][o];
            float ad0 = s.aD[btD0][o], ad1 = s.aD[btD1][o];
            #pragma unroll
            for (int e = 0; e < 2; e++) {
                if (e == 1 && !has2) break;
                const int n = (e == 0) ? n0 : n1;
                float cx0 = s.ctx4[n][0], cx1 = s.ctx4[n][1];
                float cx2 = s.ctx4[n][2], cx3 = s.ctx4[n][3];
                #pragma unroll
                for (int bb = 0; bb < BPBMAX; bb++) {
                    const float4* in4 = reinterpret_cast<const float4*>(&s.in16[bb][n][0]);
                    float4 q0 = in4[0], q1 = in4[1], q2 = in4[2], q3 = in4[3];
                    float acc_a = q0.x * wa0 + q0.y * wa1 + q0.z * wa2 + q0.w * wa3
                                + q1.x * wa4 + q1.y * wa5;
                    float acc_f = q0.x * f0  + q0.y * f1  + q0.z * f2  + q0.w * f3
                                + q1.x * f4  + q1.y * f5  + q1.z * f6  + q1.w * f7
                                + q2.x * f8  + q2.y * f9  + q2.z * f10 + q2.w * f11
                                + q3.x * f12 + q3.y * f13;
                    s.attri[bb][n][o] = acc_a;
                    float p0 = acc_f * as0;
                    float p1 = acc_f * as1;
                    float p2 = acc_f * ad0;
                    float p3 = acc_f * ad1;
                    #pragma unroll
                    for (int d = 16; d > 0; d >>= 1) {
                        p0 += __shfl_xor_sync(0xffffffffu, p0, d);
                        p1 += __shfl_xor_sync(0xffffffffu, p1, d);
                        p2 += __shfl_xor_sync(0xffffffffu, p2, d);
                        p3 += __shfl_xor_sync(0xffffffffu, p3, d);
                    }
                    if (lane == 0) {
                        s.rs[bb][n][0] = p0 + cx0;
                        s.rs[bb][n][1] = p1 + cx1;
                        s.cs2[0][bb][n] = p2 + cx2;
                        s.cs2[1][bb][n] = p3 + cx3;
                    }
                }
            }
        }
        __syncthreads();

        // ---- stage 4+5: e row (leaky, no max — logits bounded; mask folded
        //      into base -> exp=0 exactly on masked) + rowsum reciprocal ----
        for (int r = wid; r < nNN; r += NWARPS) {
            int bb = r / NN, i = r % NN;
            float ri0 = s.rs[bb][i][0], ri1 = s.rs[bb][i][1];
            int ics = (i >= NA) ? 1 : 0;
            const float* csrow = s.cs2[ics][bb];
            int j = lane;
            float v0 = (j >= NA ? ri1 : ri0) + csrow[j] + s.base[i * NN + j];
            v0 = (v0 >= 0.f) ? v0 : 0.2f * v0;
            float e0 = __expf(v0);
            int j2 = lane + 32;
            float e1 = 0.f;
            if (j2 < NN) {
                // NOTE: NA=35 > 32, so j2 in {32,33,34} is still an aqi column -> ri0!
                float v = (j2 >= NA ? ri1 : ri0) + csrow[j2] + s.base[i * NN + j2];
                v = (v >= 0.f) ? v : 0.2f * v;
                e1 = __expf(v);
            }
            s.att[bb][i][lane] = e0;
            if (j2 < NN) s.att[bb][i][j2] = e1;
            float ss = e0 + e1;
            #pragma unroll
            for (int d = 16; d > 0; d >>= 1) ss += __shfl_xor_sync(0xffffffffu, ss, d);
            if (lane == 0) s.invs[bb][i] = 1.0f / ss;
        }
        __syncthreads();

        // ---- stage 6: outvP = (attE @ attri) * invs ----
        // R5 task map (og fastest, bb warp-constant): att reads broadcast,
        // attri reads conflict-free. Scatter to KP=33-padded outvP -> 8-way.
        for (int tt = tid; tt < nT6; tt += NTHREADS) {
            int og = tt % 8;
            int ig = (tt / 8) % 27;
            int bb = tt / (27 * 8);
            int i0 = ig * 2;
            int i1 = i0 + 1;
            bool has1 = (i1 < NN);
            float4 acc0 = make_float4(0.f, 0.f, 0.f, 0.f);
            float4 acc1 = make_float4(0.f, 0.f, 0.f, 0.f);
            const float* r0 = &s.att[bb][i0][0];
            const float* r1 = &s.att[bb][has1 ? i1 : i0][0];
            const float* atrb = &s.attri[bb][0][0];
            #pragma unroll 4
            for (int j4 = 0; j4 + 4 <= NN; j4 += 4) {
                float4 a0q = *reinterpret_cast<const float4*>(&r0[j4]);
                float4 a1q = *reinterpret_cast<const float4*>(&r1[j4]);
                float4 v0 = *reinterpret_cast<const float4*>(&atrb[(j4 + 0) * HH + og * 4]);
                float4 v1 = *reinterpret_cast<const float4*>(&atrb[(j4 + 1) * HH + og * 4]);
                float4 v2 = *reinterpret_cast<const float4*>(&atrb[(j4 + 2) * HH + og * 4]);
                float4 v3 = *reinterpret_cast<const float4*>(&atrb[(j4 + 3) * HH + og * 4]);
                fma4(acc0, v0, a0q.x); fma4(acc0, v1, a0q.y);
                fma4(acc0, v2, a0q.z); fma4(acc0, v3, a0q.w);
                fma4(acc1, v0, a1q.x); fma4(acc1, v1, a1q.y);
                fma4(acc1, v2, a1q.z); fma4(acc1, v3, a1q.w);
            }
            {   // tail j = 52
                const int j = NN - 1;
                float4 v0 = *reinterpret_cast<const float4*>(&atrb[j * HH + og * 4]);
                fma4(acc0, v0, r0[j]);
                fma4(acc1, v0, r1[j]);
            }
            float inv0 = s.invs[bb][i0];
            int k0 = og * 4;
            s.outvP[i0][k0 + 0][bb] = acc0.x * inv0;
            s.outvP[i0][k0 + 1][bb] = acc0.y * inv0;
            s.outvP[i0][k0 + 2][bb] = acc0.z * inv0;
            s.outvP[i0][k0 + 3][bb] = acc0.w * inv0;
            if (has1) {
                float inv1 = s.invs[bb][i1];
                s.outvP[i1][k0 + 0][bb] = acc1.x * inv1;
                s.outvP[i1][k0 + 1][bb] = acc1.y * inv1;
                s.outvP[i1][k0 + 2][bb] = acc1.z * inv1;
                s.outvP[i1][k0 + 3][bb] = acc1.w * inv1;
            }
        }
        __syncthreads();

        // ---- stage 7: GRU, 2 same-type nodes per warp (weight reads amortized),
        //      fused r/z accumulators; 27 tasks in one round. For nb=3 blocks the
        //      bb=3 lane computes garbage confined to its own unused slot.
        //      NOTE: deterministic task<->warp map: hP rows written and re-read by
        //      the SAME warp next timestep -> no barrier after. Warps 27..31 and
        //      early finishers run ahead into next-t stage-1 LDGs.
        if (wid < 27) {
            int n0, n1; bool has2, isA;
            if (wid < 17)       { n0 = 2 * wid;              n1 = n0 + 1; has2 = true;  isA = true;  }
            else if (wid == 17) { n0 = 34;                   n1 = 34;     has2 = false; isA = true;  }
            else                { n0 = 35 + 2 * (wid - 18);  n1 = n0 + 1; has2 = true;  isA = false; }
            const float (*Wih)[96] = isA ? s.WihA : s.WihM;
            const float (*Whh)[96] = isA ? s.WhhA : s.WhhM;
            const float* bih = isA ? s.bihA : s.bihM;
            const float* bhh = isA ? s.bhhA : s.bhhM;
            float br  = bih[lane]      + bhh[lane];
            float bz  = bih[32 + lane] + bhh[32 + lane];
            float bi_n = bih[64 + lane];
            float bh_n = bhh[64 + lane];
            float4 gr0 = make_float4(br, br, br, br);
            float4 gz0 = make_float4(bz, bz, bz, bz);
            float4 gin0 = make_float4(bi_n, bi_n, bi_n, bi_n);
            float4 ghn0 = make_float4(bh_n, bh_n, bh_n, bh_n);
            float4 gr1 = gr0, gz1 = gz0, gin1 = gin0, ghn1 = ghn0;
            #pragma unroll 4
            for (int k = 0; k < HH; k++) {
                float wr = Wih[k][lane], wz = Wih[k][32 + lane], wn = Wih[k][64 + lane];
                float vr = Whh[k][lane], vz = Whh[k][32 + lane], vn = Whh[k][64 + lane];
                float4 x0 = *reinterpret_cast<const float4*>(&s.outvP[n0][k][0]);
                float4 h0 = *reinterpret_cast<const float4*>(&s.hP[n0][k][0]);
                fma4(gr0, x0, wr);  fma4(gr0, h0, vr);
                fma4(gz0, x0, wz);  fma4(gz0, h0, vz);
                fma4(gin0, x0, wn); fma4(ghn0, h0, vn);
                float4 x1 = *reinterpret_cast<const float4*>(&s.outvP[n1][k][0]);
                float4 h1 = *reinterpret_cast<const float4*>(&s.hP[n1][k][0]);
                fma4(gr1, x1, wr);  fma4(gr1, h1, vr);
                fma4(gz1, x1, wz);  fma4(gz1, h1, vz);
                fma4(gin1, x1, wn); fma4(ghn1, h1, vn);
            }
            float4 hold0 = *reinterpret_cast<const float4*>(&s.hP[n0][lane][0]);
            float4 hold1 = *reinterpret_cast<const float4*>(&s.hP[n1][lane][0]);
            float4 hnew0, hnew1;
            {
                float r, z;
                r = sigf(gr0.x); z = sigf(gz0.x);
                hnew0.x = (1.f - z) * tanh_fast(gin0.x + r * ghn0.x) + z * hold0.x;
                r = sigf(gr0.y); z = sigf(gz0.y);
                hnew0.y = (1.f - z) * tanh_fast(gin0.y + r * ghn0.y) + z * hold0.y;
                r = sigf(gr0.z); z = sigf(gz0.z);
                hnew0.z = (1.f - z) * tanh_fast(gin0.z + r * ghn0.z) + z * hold0.z;
                r = sigf(gr0.w); z = sigf(gz0.w);
                hnew0.w = (1.f - z) * tanh_fast(gin0.w + r * ghn0.w) + z * hold0.w;
                r = sigf(gr1.x); z = sigf(gz1.x);
                hnew1.x = (1.f - z) * tanh_fast(gin1.x + r * ghn1.x) + z * hold1.x;
                r = sigf(gr1.y); z = sigf(gz1.y);
                hnew1.y = (1.f - z) * tanh_fast(gin1.y + r * ghn1.y) + z * hold1.y;
                r = sigf(gr1.z); z = sigf(gz1.z);
                hnew1.z = (1.f - z) * tanh_fast(gin1.z + r * ghn1.z) + z * hold1.z;
                r = sigf(gr1.w); z = sigf(gz1.w);
                hnew1.w = (1.f - z) * tanh_fast(gin1.w + r * ghn1.w) + z * hold1.w;
            }
            __syncwarp();   // all lanes done reading hP rows n0/n1 before any write
            *reinterpret_cast<float4*>(&s.hP[n0][lane][0]) = hnew0;
            if (has2) *reinterpret_cast<float4*>(&s.hP[n1][lane][0]) = hnew1;
        }
        // no __syncthreads here; next-iter stage 1 touches only in16, and the
        // barrier after stage 1 orders everything else.
    }
    __syncthreads();

    // ---- write output: h_aqi [B,35,32] then h_meo [B,18,32] ----
    for (int idx = tid; idx < nb * NN * HH; idx += NTHREADS) {
        int o = idx & 31;
        int n = (idx >> 5) % NN;
        int bb = idx / (NN * HH);
        int b = bbase + bb;
        float v = s.hP[n][o][bb];
        if (n < NA) A.out[((size_t)b * NA + n) * HH + o] = v;
        else        A.out[(size_t)BN * NA * HH + ((size_t)b * NM + (n - NA)) * HH + o] = v;
    }
}

extern "C" void kernel_launch(void* const* d_in, const int* in_sizes, int n_in,
                              void* d_out, int out_size) {
    (void)in_sizes; (void)n_in; (void)out_size;
    const float* X_aqi = (const float*)d_in[0];
    const float* X_meo = (const float*)d_in[1];
    const float* ctx   = (const float*)d_in[2];
    const float* adj   = (const float*)d_in[3];
    const float* adjn  = (const float*)d_in[4];
    const float* e_ai  = (const float*)d_in[5];
    const float* e_amo = (const float*)d_in[6];
    const float* e_awd = (const float*)d_in[7];
    const float* e_ah  = (const float*)d_in[8];
    const float* e_mw  = (const float*)d_in[9];
    const float* e_mid = (const float*)d_in[10];
    const float* e_mmo = (const float*)d_in[11];
    const float* e_mwd = (const float*)d_in[12];
    const float* e_mh  = (const float*)d_in[13];
    const float* W_xa  = (const float*)d_in[14];
    const float* W_xm  = (const float*)d_in[15];
    const float* W_ua  = (const float*)d_in[16];
    const float* W_um  = (const float*)d_in[17];
    const float* a0    = (const float*)d_in[18];
    const float* a1    = (const float*)d_in[19];
    const float* a2    = (const float*)d_in[20];
    const float* a3    = (const float*)d_in[21];
    const float* wihA  = (const float*)d_in[22];
    const float* whhA  = (const float*)d_in[23];
    const float* bihA  = (const float*)d_in[24];
    const float* bhhA  = (const float*)d_in[25];
    const float* wihM  = (const float*)d_in[26];
    const float* whhM  = (const float*)d_in[27];
    const float* bihM  = (const float*)d_in[28];
    const float* bhhM  = (const float*)d_in[29];
    const int*   EXa   = (const int*)d_in[30];
    const int*   EXm   = (const int*)d_in[31];

    setup_kernel<<<1, 256>>>(adj, adjn, ctx, a0, a1, a2, a3);

    Args A;
    A.X_aqi = X_aqi; A.X_meo = X_meo;
    A.e_ai = e_ai; A.e_amo = e_amo; A.e_awd = e_awd; A.e_ah = e_ah;
    A.e_mw = e_mw; A.e_mid = e_mid; A.e_mmo = e_mmo; A.e_mwd = e_mwd; A.e_mh = e_mh;
    A.W_xa = W_xa; A.W_xm = W_xm; A.W_ua = W_ua; A.W_um = W_um;
    A.a0 = a0; A.a1 = a1; A.a2 = a2; A.a3 = a3;
    A.wihA = wihA; A.whhA = whhA; A.bihA = bihA; A.bhhA = bhhA;
    A.wihM = wihM; A.whhM = whhM; A.bihM = bihM; A.bhhM = bhhM;
    A.EXa = EXa; A.EXm = EXm;
    A.out = (float*)d_out;

    int smem = (int)sizeof(SmemLayout);
    cudaFuncSetAttribute(chgat_gru_kernel, cudaFuncAttributeMaxDynamicSharedMemorySize, smem);
    chgat_gru_kernel<<<NBLOCKS, NTHREADS, smem>>>(A);
}